// round 1
// baseline (speedup 1.0000x reference)
#include <cuda_runtime.h>
#include <math.h>

// Problem constants
#define B_   2
#define C_   128
#define T_   4
#define NH   32
#define D_   4
#define N_   1024    // patch tokens = T * 16 * 16
#define P_   16      // pixels per patch
#define TBL  6727    // (2T-1)*(2h-1)*(2w-1) = 7*31*31
#define PERC 16384   // elements per (b,c) = N_*P_

// ---------------- scratch (device globals; no allocation allowed) ----------------
__device__ float g_q[B_*C_*PERC];       // raw projected q, patch layout [b][c][n][p]
__device__ float g_k[B_*C_*PERC];
__device__ float g_v[B_*C_*PERC];
__device__ float g_qpool[B_*C_*N_];     // patch-mean of raw q
__device__ float g_kpool[B_*C_*N_];
__device__ float g_stats[3*B_*NH*2];    // per-tensor, per-(b,group) sum / sumsq
__device__ float g_ms[3*B_*NH*2];       // mu / rsig

// ---------------- kernel 0: zero stats ----------------
__global__ void zero_stats_kernel() {
    int i = threadIdx.x;
    if (i < 3*B_*NH*2) g_stats[i] = 0.f;
}

// ---------------- kernel 1: projections (3x GEMM 128x128 @ 32768 cols) ----------------
// Y[o][j] = sum_c W[o][c] * X[c][j], j = b*16384 + n*16 + p  (patch-ordered positions)
__global__ void proj_kernel(const float* __restrict__ x,
                            const float* __restrict__ Wq,
                            const float* __restrict__ Wk,
                            const float* __restrict__ Wv) {
    extern __shared__ float sm[];
    float* Wsm = sm;            // [c][o]  128*128
    float* Xsm = sm + 16384;    // [c][68] padded

    int tid  = threadIdx.x;
    int proj = blockIdx.y;
    const float* Wm = (proj == 0) ? Wq : ((proj == 1) ? Wk : Wv);
    float* out      = (proj == 0) ? g_q : ((proj == 1) ? g_k : g_v);

    int j0 = blockIdx.x * 64;       // 64 positions = 4 whole patches; never crosses b
    int b  = j0 >> 14;
    int r0 = j0 & 16383;

    // load W transposed: Wsm[c][o]
    for (int e = tid; e < 16384; e += 256) {
        int o = e >> 7, c = e & 127;
        Wsm[c*128 + o] = Wm[e];
    }
    // gather X tile in patch order
    for (int e = tid; e < 8192; e += 256) {
        int c = e >> 6, jl = e & 63;
        int r = r0 + jl;
        int n = r >> 4, p = r & 15;
        int t = n >> 8, hi = (n >> 4) & 15, wi = n & 15;
        int sh = p >> 2, sw = p & 3;
        Xsm[c*68 + jl] = x[(b*128 + c)*16384 + t*4096 + (hi*4 + sh)*64 + wi*4 + sw];
    }
    __syncthreads();

    int og = tid >> 4, jg = tid & 15;
    int o0 = og * 8, jl0 = jg * 4;
    float acc[8][4];
    #pragma unroll
    for (int i = 0; i < 8; i++)
        #pragma unroll
        for (int j = 0; j < 4; j++) acc[i][j] = 0.f;

    #pragma unroll 4
    for (int c = 0; c < 128; c++) {
        float4 w0 = *(float4*)&Wsm[c*128 + o0];
        float4 w1 = *(float4*)&Wsm[c*128 + o0 + 4];
        float4 xv = *(float4*)&Xsm[c*68 + jl0];
        float wr[8] = {w0.x, w0.y, w0.z, w0.w, w1.x, w1.y, w1.z, w1.w};
        float xr[4] = {xv.x, xv.y, xv.z, xv.w};
        #pragma unroll
        for (int i = 0; i < 8; i++)
            #pragma unroll
            for (int j = 0; j < 4; j++) acc[i][j] += wr[i] * xr[j];
    }

    #pragma unroll
    for (int i = 0; i < 8; i++) {
        float4 v = make_float4(acc[i][0], acc[i][1], acc[i][2], acc[i][3]);
        *(float4*)&out[(b*128 + o0 + i)*16384 + r0 + jl0] = v;
    }
}

// ---------------- kernel 2: patch pooling + groupnorm stats ----------------
// one block per (b,c) row of 16384 elements; grid.y selects q/k/v
__global__ void poolstats_kernel() {
    int tid = threadIdx.x;
    int bc = blockIdx.x;            // b*128 + c
    int tensor = blockIdx.y;
    const float* src = (tensor == 0) ? g_q : ((tensor == 1) ? g_k : g_v);

    const float4* s4 = (const float4*)(src + (size_t)bc * 16384 + tid * 64);
    float lsum = 0.f, lsq = 0.f;
    #pragma unroll
    for (int pi = 0; pi < 4; pi++) {
        float ps = 0.f;
        #pragma unroll
        for (int e = 0; e < 4; e++) {
            float4 v = s4[pi*4 + e];
            ps   += v.x + v.y + v.z + v.w;
            lsq  += v.x*v.x + v.y*v.y + v.z*v.z + v.w*v.w;
        }
        lsum += ps;
        if (tensor == 0) g_qpool[bc*1024 + tid*4 + pi] = ps * (1.f/16.f);
        else if (tensor == 1) g_kpool[bc*1024 + tid*4 + pi] = ps * (1.f/16.f);
    }

    __shared__ float rs[256], rq[256];
    rs[tid] = lsum; rq[tid] = lsq;
    __syncthreads();
    for (int s = 128; s > 0; s >>= 1) {
        if (tid < s) { rs[tid] += rs[tid + s]; rq[tid] += rq[tid + s]; }
        __syncthreads();
    }
    if (tid == 0) {
        int b = bc >> 7, g = (bc & 127) >> 2;
        atomicAdd(&g_stats[((tensor*B_ + b)*NH + g)*2 + 0], rs[0]);
        atomicAdd(&g_stats[((tensor*B_ + b)*NH + g)*2 + 1], rq[0]);
    }
}

// ---------------- kernel 3: finalize mu / rsig ----------------
__global__ void finalize_stats_kernel() {
    int i = threadIdx.x;
    if (i < 3*B_*NH) {
        float s = g_stats[i*2], q = g_stats[i*2 + 1];
        float mu  = s * (1.f/65536.f);
        float var = q * (1.f/65536.f) - mu*mu;
        g_ms[i*2]     = mu;
        g_ms[i*2 + 1] = rsqrtf(var + 1e-5f);
    }
}

// ---------------- kernel 4: fused flash attention + rel-bias + v-affine epilogue ----------------
// block = 256 threads, handles 128 query tokens of one (b,head); streams m in 8 chunks of 128.
__global__ void attn_kernel(const float* __restrict__ gq_g, const float* __restrict__ gq_b,
                            const float* __restrict__ gk_g, const float* __restrict__ gk_b,
                            const float* __restrict__ gv_g, const float* __restrict__ gv_b,
                            const float* __restrict__ rel_table,
                            const int*   __restrict__ rel_index,
                            float* __restrict__ out) {
    extern __shared__ float sm[];
    float* ksm  = sm;               // [d][1024]   4096
    float* qsm  = ksm + 4096;       // [d][128]    512   (pre-scaled by 1/sqrt(d))
    float* tbl  = qsm + 512;        // 6728 (padded)
    float* Ssm  = tbl + 6728;       // [128][129]  16512
    float* Vsm  = Ssm + 16512;      // [m=128][dp=64] 8192
    float* rowC = Vsm + 8192;       // 128 (softmax correction factors)
    float* rowL = rowC + 128;       // 128 (final denominators)

    int tid  = threadIdx.x;
    int bh   = blockIdx.x;
    int b    = bh >> 5, head = bh & 31;
    int n0   = blockIdx.y << 7;
    int c0   = head * 4;

    float muq = g_ms[((0*B_ + b)*NH + head)*2], rsq = g_ms[((0*B_ + b)*NH + head)*2 + 1];
    float muk = g_ms[((1*B_ + b)*NH + head)*2], rsk = g_ms[((1*B_ + b)*NH + head)*2 + 1];
    float muv = g_ms[((2*B_ + b)*NH + head)*2], rsv = g_ms[((2*B_ + b)*NH + head)*2 + 1];

    // normalized pooled keys for the whole head
    for (int e = tid; e < 4096; e += 256) {
        int d = e >> 10, m = e & 1023;
        float a  = gk_g[c0 + d] * rsk;
        float bb = gk_b[c0 + d] - muk * a;
        ksm[e] = a * g_kpool[(b*128 + c0 + d)*1024 + m] + bb;
    }
    // normalized pooled queries for this tile, scale 1/sqrt(d)=0.5 folded in
    for (int e = tid; e < 512; e += 256) {
        int d = e >> 7, q = e & 127;
        float a  = gq_g[c0 + d] * rsq;
        float bb = gq_b[c0 + d] - muq * a;
        qsm[e] = 0.5f * (a * g_qpool[(b*128 + c0 + d)*1024 + n0 + q] + bb);
    }
    for (int e = tid; e < TBL; e += 256) tbl[e] = rel_table[head*TBL + e];
    __syncthreads();

    int qg = tid >> 3, dpg = tid & 7;
    int q0 = qg * 4, dp0 = dpg * 8;
    float o_[4][8];
    #pragma unroll
    for (int i = 0; i < 4; i++)
        #pragma unroll
        for (int j = 0; j < 8; j++) o_[i][j] = 0.f;

    float m_i = -3.0e38f, l_i = 0.f;     // per-row softmax state (threads 0..127)

    for (int mc = 0; mc < 8; mc++) {
        int m0 = mc << 7;
        // ---- scores: QK^T (K=4) + relative position bias ----
        #pragma unroll 4
        for (int e = tid; e < 16384; e += 256) {
            int q = e >> 7, m = e & 127;
            int gm = m0 + m;
            float s = qsm[q]       * ksm[gm]
                    + qsm[128 + q] * ksm[1024 + gm]
                    + qsm[256 + q] * ksm[2048 + gm]
                    + qsm[384 + q] * ksm[3072 + gm];
            s += tbl[rel_index[(n0 + q)*1024 + gm]];
            Ssm[q*129 + m] = s;
        }
        // ---- stage V chunk: Vsm[m][dp], dp = d*16+p ----
        #pragma unroll 4
        for (int e = tid; e < 8192; e += 256) {
            int m = e >> 6, dp = e & 63;
            int d = dp >> 4, p = dp & 15;
            Vsm[e] = g_v[(b*128 + c0 + d)*16384 + ((m0 + m) << 4) + p];
        }
        __syncthreads();

        // ---- online softmax (one row per thread, threads 0..127) ----
        if (tid < 128) {
            float* row = &Ssm[tid*129];
            float cmax = -3.0e38f;
            #pragma unroll 8
            for (int m = 0; m < 128; m++) cmax = fmaxf(cmax, row[m]);
            float mnew = fmaxf(m_i, cmax);
            float corr = __expf(m_i - mnew);
            float rsum = 0.f;
            #pragma unroll 8
            for (int m = 0; m < 128; m++) {
                float pv = __expf(row[m] - mnew);
                row[m] = pv;
                rsum += pv;
            }
            l_i = l_i * corr + rsum;
            m_i = mnew;
            rowC[tid] = corr;
        }
        __syncthreads();

        // ---- rescale accumulators, then O += P @ V ----
        float cc[4];
        #pragma unroll
        for (int qi = 0; qi < 4; qi++) cc[qi] = rowC[q0 + qi];
        #pragma unroll
        for (int qi = 0; qi < 4; qi++)
            #pragma unroll
            for (int e = 0; e < 8; e++) o_[qi][e] *= cc[qi];

        #pragma unroll 4
        for (int m = 0; m < 128; m++) {
            float4 v0 = *(float4*)&Vsm[m*64 + dp0];
            float4 v1 = *(float4*)&Vsm[m*64 + dp0 + 4];
            #pragma unroll
            for (int qi = 0; qi < 4; qi++) {
                float pv = Ssm[(q0 + qi)*129 + m];
                o_[qi][0] += pv * v0.x; o_[qi][1] += pv * v0.y;
                o_[qi][2] += pv * v0.z; o_[qi][3] += pv * v0.w;
                o_[qi][4] += pv * v1.x; o_[qi][5] += pv * v1.y;
                o_[qi][6] += pv * v1.z; o_[qi][7] += pv * v1.w;
            }
        }
        __syncthreads();
    }

    if (tid < 128) rowL[tid] = l_i;
    __syncthreads();

    // ---- epilogue: divide by l, apply v GroupNorm affine, un-patch to (b,c,t,H,W) ----
    #pragma unroll
    for (int qi = 0; qi < 4; qi++) {
        int n = n0 + q0 + qi;
        float invl = 1.f / rowL[q0 + qi];
        int t = n >> 8, hi = (n >> 4) & 15, wi = n & 15;
        #pragma unroll
        for (int e = 0; e < 8; e++) {
            int dp = dp0 + e;
            int d = dp >> 4, p = dp & 15;
            int sh = p >> 2, sw = p & 3;
            float a  = gv_g[c0 + d] * rsv;
            float bb = gv_b[c0 + d] - muv * a;
            float val = a * (o_[qi][e] * invl) + bb;
            out[(b*128 + c0 + d)*16384 + t*4096 + (hi*4 + sh)*64 + wi*4 + sw] = val;
        }
    }
}

// ---------------- launcher ----------------
extern "C" void kernel_launch(void* const* d_in, const int* in_sizes, int n_in,
                              void* d_out, int out_size) {
    (void)in_sizes; (void)n_in; (void)out_size;
    const float* x    = (const float*)d_in[0];
    const float* Wq   = (const float*)d_in[1];
    const float* Wk   = (const float*)d_in[2];
    const float* Wv   = (const float*)d_in[3];
    const float* gq_g = (const float*)d_in[4];
    const float* gq_b = (const float*)d_in[5];
    const float* gk_g = (const float*)d_in[6];
    const float* gk_b = (const float*)d_in[7];
    const float* gv_g = (const float*)d_in[8];
    const float* gv_b = (const float*)d_in[9];
    const float* rel_table = (const float*)d_in[10];
    const int*   rel_index = (const int*)d_in[11];
    float* out = (float*)d_out;

    const int PROJ_SMEM = (16384 + 128*68) * 4;                 // 100352 B
    const int ATTN_SMEM = (4096 + 512 + 6728 + 16512 + 8192 + 256) * 4;  // 145184 B
    cudaFuncSetAttribute(proj_kernel, cudaFuncAttributeMaxDynamicSharedMemorySize, PROJ_SMEM);
    cudaFuncSetAttribute(attn_kernel, cudaFuncAttributeMaxDynamicSharedMemorySize, ATTN_SMEM);

    zero_stats_kernel<<<1, 512>>>();
    proj_kernel<<<dim3(512, 3), 256, PROJ_SMEM>>>(x, Wq, Wk, Wv);
    poolstats_kernel<<<dim3(256, 3), 256>>>();
    finalize_stats_kernel<<<1, 256>>>();
    attn_kernel<<<dim3(64, 8), 256, ATTN_SMEM>>>(gq_g, gq_b, gk_g, gk_b,
                                                 gv_g, gv_b, rel_table, rel_index, out);
}

// round 3
// speedup vs baseline: 3.6543x; 3.6543x over previous
#include <cuda_runtime.h>
#include <math.h>
#include <stdint.h>

// Problem constants
#define B_   2
#define C_   128
#define T_   4
#define NH   32
#define D_   4
#define N_   1024
#define P_   16
#define TBL  6727
#define PERC 16384

// ---------------- scratch ----------------
__device__ float g_q[B_*C_*PERC];
__device__ float g_k[B_*C_*PERC];
__device__ float g_v[B_*C_*PERC];
__device__ float g_qpool[B_*C_*N_];
__device__ float g_kpool[B_*C_*N_];
__device__ float g_stats[3*B_*NH*2];
__device__ float g_ms[3*B_*NH*2];

// ---------------- helpers ----------------
__device__ __forceinline__ uint32_t f2tf32(float x) {
    uint32_t u;
    asm("cvt.rna.tf32.f32 %0, %1;" : "=r"(u) : "f"(x));
    return u;
}
__device__ __forceinline__ void mma_tf32(float c[4], uint32_t a0, uint32_t a1,
                                         uint32_t a2, uint32_t a3,
                                         uint32_t b0, uint32_t b1) {
    asm volatile(
        "mma.sync.aligned.m16n8k8.row.col.f32.tf32.tf32.f32 "
        "{%0,%1,%2,%3}, {%4,%5,%6,%7}, {%8,%9}, {%0,%1,%2,%3};"
        : "+f"(c[0]), "+f"(c[1]), "+f"(c[2]), "+f"(c[3])
        : "r"(a0), "r"(a1), "r"(a2), "r"(a3), "r"(b0), "r"(b1));
}

// smem float offsets for attn kernel
#define F_KSM  0        // [4][1024]
#define F_QSM  4096     // [128][4]
#define F_TBL  4608     // 6728
#define F_SSM  11336    // P tf32 bits [128][68]; reused as out-stage floats
#define F_VSM  20040    // V tf32 bits [64][72]; reused as reduce scratch
#define F_SUMS 24648    // [128]
#define F_TOT  24776
#define ATTN_SMEM (F_TOT*4)

// ---------------- kernel 0: zero stats ----------------
__global__ void zero_stats_kernel() {
    int i = threadIdx.x;
    if (i < 3*B_*NH*2) g_stats[i] = 0.f;
}

// ---------------- kernel 1: projections ----------------
__global__ void proj_kernel(const float* __restrict__ x,
                            const float* __restrict__ Wq,
                            const float* __restrict__ Wk,
                            const float* __restrict__ Wv) {
    extern __shared__ float sm[];
    float* Wsm = sm;
    float* Xsm = sm + 16384;

    int tid  = threadIdx.x;
    int proj = blockIdx.y;
    const float* Wm = (proj == 0) ? Wq : ((proj == 1) ? Wk : Wv);
    float* out      = (proj == 0) ? g_q : ((proj == 1) ? g_k : g_v);

    int j0 = blockIdx.x * 64;
    int b  = j0 >> 14;
    int r0 = j0 & 16383;

    for (int e = tid; e < 16384; e += 256) {
        int o = e >> 7, c = e & 127;
        Wsm[c*128 + o] = Wm[e];
    }
    for (int e = tid; e < 8192; e += 256) {
        int c = e >> 6, jl = e & 63;
        int r = r0 + jl;
        int n = r >> 4, p = r & 15;
        int t = n >> 8, hi = (n >> 4) & 15, wi = n & 15;
        int sh = p >> 2, sw = p & 3;
        Xsm[c*68 + jl] = x[(b*128 + c)*16384 + t*4096 + (hi*4 + sh)*64 + wi*4 + sw];
    }
    __syncthreads();

    int og = tid >> 4, jg = tid & 15;
    int o0 = og * 8, jl0 = jg * 4;
    float acc[8][4];
    #pragma unroll
    for (int i = 0; i < 8; i++)
        #pragma unroll
        for (int j = 0; j < 4; j++) acc[i][j] = 0.f;

    #pragma unroll 4
    for (int c = 0; c < 128; c++) {
        float4 w0 = *(float4*)&Wsm[c*128 + o0];
        float4 w1 = *(float4*)&Wsm[c*128 + o0 + 4];
        float4 xv = *(float4*)&Xsm[c*68 + jl0];
        float wr[8] = {w0.x, w0.y, w0.z, w0.w, w1.x, w1.y, w1.z, w1.w};
        float xr[4] = {xv.x, xv.y, xv.z, xv.w};
        #pragma unroll
        for (int i = 0; i < 8; i++)
            #pragma unroll
            for (int j = 0; j < 4; j++) acc[i][j] += wr[i] * xr[j];
    }

    #pragma unroll
    for (int i = 0; i < 8; i++) {
        float4 v = make_float4(acc[i][0], acc[i][1], acc[i][2], acc[i][3]);
        *(float4*)&out[(b*128 + o0 + i)*16384 + r0 + jl0] = v;
    }
}

// ---------------- kernel 2: pooling + stats ----------------
__global__ void poolstats_kernel() {
    int tid = threadIdx.x;
    int bc = blockIdx.x;
    int tensor = blockIdx.y;
    const float* src = (tensor == 0) ? g_q : ((tensor == 1) ? g_k : g_v);

    const float4* s4 = (const float4*)(src + (size_t)bc * 16384 + tid * 64);
    float lsum = 0.f, lsq = 0.f;
    #pragma unroll
    for (int pi = 0; pi < 4; pi++) {
        float ps = 0.f;
        #pragma unroll
        for (int e = 0; e < 4; e++) {
            float4 v = s4[pi*4 + e];
            ps  += v.x + v.y + v.z + v.w;
            lsq += v.x*v.x + v.y*v.y + v.z*v.z + v.w*v.w;
        }
        lsum += ps;
        if (tensor == 0) g_qpool[bc*1024 + tid*4 + pi] = ps * (1.f/16.f);
        else if (tensor == 1) g_kpool[bc*1024 + tid*4 + pi] = ps * (1.f/16.f);
    }

    __shared__ float rs[256], rq[256];
    rs[tid] = lsum; rq[tid] = lsq;
    __syncthreads();
    for (int s = 128; s > 0; s >>= 1) {
        if (tid < s) { rs[tid] += rs[tid + s]; rq[tid] += rq[tid + s]; }
        __syncthreads();
    }
    if (tid == 0) {
        int b = bc >> 7, g = (bc & 127) >> 2;
        atomicAdd(&g_stats[((tensor*B_ + b)*NH + g)*2 + 0], rs[0]);
        atomicAdd(&g_stats[((tensor*B_ + b)*NH + g)*2 + 1], rq[0]);
    }
}

// ---------------- kernel 3: finalize mu / rsig ----------------
__global__ void finalize_stats_kernel() {
    int i = threadIdx.x;
    if (i < 3*B_*NH) {
        float s = g_stats[i*2], q = g_stats[i*2 + 1];
        float mu  = s * (1.f/65536.f);
        float var = q * (1.f/65536.f) - mu*mu;
        g_ms[i*2]     = mu;
        g_ms[i*2 + 1] = rsqrtf(var + 1e-5f);
    }
}

// ---------------- kernel 4: attention, PV on mma.sync tf32 ----------------
__global__ void __launch_bounds__(256, 2)
attn_kernel(const float* __restrict__ gq_g, const float* __restrict__ gq_b,
            const float* __restrict__ gk_g, const float* __restrict__ gk_b,
            const float* __restrict__ gv_g, const float* __restrict__ gv_b,
            const float* __restrict__ rel_table,
            float* __restrict__ out) {
    extern __shared__ float smf[];
    float* ksm = smf + F_KSM;
    float* qsm = smf + F_QSM;
    float* tbl = smf + F_TBL;
    uint32_t* Ssm = (uint32_t*)(smf + F_SSM);   // [128][68] tf32 P
    uint32_t* Vsm = (uint32_t*)(smf + F_VSM);   // [64][72]  tf32 V^T-chunk
    float* sums = smf + F_SUMS;

    int tid  = threadIdx.x;
    int w    = tid >> 5, lane = tid & 31;
    int bh   = blockIdx.x;
    int b    = bh >> 5, head = bh & 31;
    int n0   = blockIdx.y << 7;
    int c0   = head * 4;

    float muq = g_ms[((0*B_ + b)*NH + head)*2], rsq = g_ms[((0*B_ + b)*NH + head)*2 + 1];
    float muk = g_ms[((1*B_ + b)*NH + head)*2], rsk = g_ms[((1*B_ + b)*NH + head)*2 + 1];
    float muv = g_ms[((2*B_ + b)*NH + head)*2], rsv = g_ms[((2*B_ + b)*NH + head)*2 + 1];

    // normalized pooled keys [d][1024]
    for (int e = tid; e < 4096; e += 256) {
        int d = e >> 10, m = e & 1023;
        float a  = gk_g[c0 + d] * rsk;
        float bb = gk_b[c0 + d] - muk * a;
        ksm[e] = a * g_kpool[(b*128 + c0 + d)*1024 + m] + bb;
    }
    // normalized pooled queries [q][d], 0.5 scale folded
    for (int e = tid; e < 512; e += 256) {
        int q = e >> 2, d = e & 3;
        float a  = gq_g[c0 + d] * rsq;
        float bb = gq_b[c0 + d] - muq * a;
        qsm[e] = 0.5f * (a * g_qpool[(b*128 + c0 + d)*1024 + n0 + q] + bb);
    }
    for (int e = tid; e < TBL; e += 256) tbl[e] = rel_table[head*TBL + e];
    __syncthreads();

    // per-thread score role: fixed m within chunk, 32 q rows
    int mloc = tid & 63;          // 0..63
    int qg   = tid >> 6;          // 0..3 ; q = qg + 4j
    float psum[32];
    #pragma unroll
    for (int j = 0; j < 32; j++) psum[j] = 0.f;

    // per-warp mma role: 4 q-tiles x 2 n-halves
    int qt = w >> 1, nh = w & 1;
    int r  = lane >> 2, cl = lane & 3;
    float acc[2][4][4];
    #pragma unroll
    for (int i2 = 0; i2 < 2; i2++)
        #pragma unroll
        for (int nt = 0; nt < 4; nt++)
            #pragma unroll
            for (int ci = 0; ci < 4; ci++) acc[i2][nt][ci] = 0.f;

    const float* vb = g_v + (size_t)(b*128 + c0) * 16384;

    // query-side rel coords for this thread's q rows (n changes with j)
    #pragma unroll 1
    for (int ch = 0; ch < 16; ch++) {
        int m0 = ch << 6;

        // ---- stage V chunk [64 m][64 dp] as tf32 ----
        #pragma unroll
        for (int it = 0; it < 16; it++) {
            int e = tid + it*256;
            int m = e >> 6, dp = e & 63;
            int d = dp >> 4, p = dp & 15;
            float v = vb[(size_t)d*16384 + (m0 + m)*16 + p];
            Vsm[m*72 + dp] = f2tf32(v);
        }

        // ---- scores -> exp -> Ssm + psum ----
        {
            int gm = m0 + mloc;
            float kv0 = ksm[gm];
            float kv1 = ksm[1024 + gm];
            float kv2 = ksm[2048 + gm];
            float kv3 = ksm[3072 + gm];
            int t2 = gm >> 8, y2 = (gm >> 4) & 15, x2 = gm & 15;
            #pragma unroll
            for (int j = 0; j < 32; j++) {
                int q = qg + 4*j;
                int n = n0 + q;
                int t1 = n >> 8, y1 = (n >> 4) & 15, x1 = n & 15;
                int idx = ((t1 - t2 + 3)*31 + (y1 - y2 + 15))*31 + (x1 - x2 + 15);
                float4 qv = *(float4*)&qsm[q*4];
                float s = qv.x*kv0 + qv.y*kv1 + qv.z*kv2 + qv.w*kv3 + tbl[idx];
                float p = __expf(s);
                psum[j] += p;
                Ssm[q*68 + mloc] = f2tf32(p);
            }
        }
        __syncthreads();

        // ---- mma: O[128x64] += P[128x64ch] @ V[64ch x 64] ----
        #pragma unroll
        for (int ks = 0; ks < 8; ks++) {
            uint32_t a[2][4];
            #pragma unroll
            for (int i2 = 0; i2 < 2; i2++) {
                int row = qt*32 + i2*16;
                a[i2][0] = Ssm[(row + r)*68 + ks*8 + cl];
                a[i2][1] = Ssm[(row + r + 8)*68 + ks*8 + cl];
                a[i2][2] = Ssm[(row + r)*68 + ks*8 + cl + 4];
                a[i2][3] = Ssm[(row + r + 8)*68 + ks*8 + cl + 4];
            }
            #pragma unroll
            for (int nt = 0; nt < 4; nt++) {
                int nb = nh*32 + nt*8;
                uint32_t b0 = Vsm[(ks*8 + cl)*72 + nb + r];
                uint32_t b1 = Vsm[(ks*8 + cl + 4)*72 + nb + r];
                mma_tf32(acc[0][nt], a[0][0], a[0][1], a[0][2], a[0][3], b0, b1);
                mma_tf32(acc[1][nt], a[1][0], a[1][1], a[1][2], a[1][3], b0, b1);
            }
        }
        __syncthreads();
    }

    // ---- row-sum reduction ----
    #pragma unroll
    for (int j = 0; j < 32; j++) {
        float v = psum[j];
        v += __shfl_xor_sync(0xffffffffu, v, 1);
        v += __shfl_xor_sync(0xffffffffu, v, 2);
        v += __shfl_xor_sync(0xffffffffu, v, 4);
        v += __shfl_xor_sync(0xffffffffu, v, 8);
        v += __shfl_xor_sync(0xffffffffu, v, 16);
        psum[j] = v;
    }
    float* scr = (float*)Vsm;
    if (lane == 0) {
        #pragma unroll
        for (int j = 0; j < 32; j++) scr[w*32 + j] = psum[j];
    }
    __syncthreads();
    if (tid < 128) {
        int g = tid & 3, j = tid >> 2;
        sums[tid] = scr[(2*g)*32 + j] + scr[(2*g + 1)*32 + j];
    }
    __syncthreads();

    // ---- epilogue: normalize + v-affine -> stage ----
    float av[4], bv[4];
    #pragma unroll
    for (int d = 0; d < 4; d++) {
        av[d] = gv_g[c0 + d] * rsv;
        bv[d] = gv_b[c0 + d] - muv * av[d];
    }
    float* stage = (float*)Ssm;
    {
        float invl[2][2];
        #pragma unroll
        for (int i2 = 0; i2 < 2; i2++)
            #pragma unroll
            for (int h8 = 0; h8 < 2; h8++)
                invl[i2][h8] = 1.f / sums[qt*32 + i2*16 + r + h8*8];
        #pragma unroll
        for (int i2 = 0; i2 < 2; i2++)
            #pragma unroll
            for (int nt = 0; nt < 4; nt++)
                #pragma unroll
                for (int ci = 0; ci < 4; ci++) {
                    int h8  = (ci >> 1) & 1;
                    int row = qt*32 + i2*16 + r + h8*8;
                    int col = nh*32 + nt*8 + cl*2 + (ci & 1);
                    int d   = col >> 4;
                    stage[row*68 + col] = av[d]*(acc[i2][nt][ci]*invl[i2][h8]) + bv[d];
                }
    }
    __syncthreads();

    // ---- coalesced global write ----
    int t  = n0 >> 8;
    int hi0 = (n0 >> 4) & 15;
    #pragma unroll
    for (int it = 0; it < 32; it++) {
        int e = tid + it*256;
        int rr = e >> 6, cc = e & 63;
        int d = rr >> 5, hl = (rr >> 2) & 7, sh = rr & 3;
        int q = hl*16 + (cc >> 2);
        int dp = d*16 + sh*4 + (cc & 3);
        out[(size_t)(b*128 + c0 + d)*16384 + t*4096 + ((hi0 + hl)*4 + sh)*64 + cc]
            = stage[q*68 + dp];
    }
}

// ---------------- launcher ----------------
extern "C" void kernel_launch(void* const* d_in, const int* in_sizes, int n_in,
                              void* d_out, int out_size) {
    (void)in_sizes; (void)n_in; (void)out_size;
    const float* x    = (const float*)d_in[0];
    const float* Wq   = (const float*)d_in[1];
    const float* Wk   = (const float*)d_in[2];
    const float* Wv   = (const float*)d_in[3];
    const float* gq_g = (const float*)d_in[4];
    const float* gq_b = (const float*)d_in[5];
    const float* gk_g = (const float*)d_in[6];
    const float* gk_b = (const float*)d_in[7];
    const float* gv_g = (const float*)d_in[8];
    const float* gv_b = (const float*)d_in[9];
    const float* rel_table = (const float*)d_in[10];
    float* out = (float*)d_out;

    const int PROJ_SMEM = (16384 + 128*68) * 4;
    cudaFuncSetAttribute(proj_kernel, cudaFuncAttributeMaxDynamicSharedMemorySize, PROJ_SMEM);
    cudaFuncSetAttribute(attn_kernel, cudaFuncAttributeMaxDynamicSharedMemorySize, ATTN_SMEM);

    zero_stats_kernel<<<1, 512>>>();
    proj_kernel<<<dim3(512, 3), 256, PROJ_SMEM>>>(x, Wq, Wk, Wv);
    poolstats_kernel<<<dim3(256, 3), 256>>>();
    finalize_stats_kernel<<<1, 256>>>();
    attn_kernel<<<dim3(64, 8), 256, ATTN_SMEM>>>(gq_g, gq_b, gk_g, gk_b,
                                                 gv_g, gv_b, rel_table, out);
}

// round 4
// speedup vs baseline: 6.4601x; 1.7678x over previous
#include <cuda_runtime.h>
#include <cuda_fp16.h>
#include <math.h>
#include <stdint.h>

// Problem constants
#define B_   2
#define NH   32
#define TBL  6727

// ---------------- scratch ----------------
__device__ __half g_vh[B_*128*16384];      // projected v, fp16, patch layout [b][c][n*16+p]
__device__ float g_qpool[B_*128*1024];
__device__ float g_kpool[B_*128*1024];
__device__ float g_stats[3*B_*NH*2];

// ---------------- helpers ----------------
__device__ __forceinline__ void mma_f16(float c[4], uint32_t a0, uint32_t a1,
                                        uint32_t a2, uint32_t a3,
                                        uint32_t b0, uint32_t b1) {
    asm volatile(
        "mma.sync.aligned.m16n8k16.row.col.f32.f16.f16.f32 "
        "{%0,%1,%2,%3}, {%4,%5,%6,%7}, {%8,%9}, {%0,%1,%2,%3};"
        : "+f"(c[0]), "+f"(c[1]), "+f"(c[2]), "+f"(c[3])
        : "r"(a0), "r"(a1), "r"(a2), "r"(a3), "r"(b0), "r"(b1));
}

// ---------------- kernel 0: zero stats ----------------
__global__ void zero_stats_kernel() {
    int i = threadIdx.x;
    if (i < 3*B_*NH*2) g_stats[i] = 0.f;
}

// ---------------- kernel 1: fused projections + pooling + GN stats + v store ----------------
// One CTA = 128 j positions (8 whole patches) x all 128 out channels x 3 projections.
// X tile loaded once (fp16), W streamed per projection. Epilogue pools q/k (fp32),
// accumulates GroupNorm sum/sumsq per (b,group), stores v as fp16.
#define PRJ_XS 0                 // half [j=128][136], col swizz c^(2*(j>>4))
#define PRJ_WS 34816             // half [o=128][136]
#define PRJ_SG 69632             // float [32][2]
#define PRJ_SMEM (69632 + 256)

__global__ void __launch_bounds__(256, 2)
proj_kernel(const float* __restrict__ x,
            const float* __restrict__ Wq,
            const float* __restrict__ Wk,
            const float* __restrict__ Wv) {
    extern __shared__ char smc[];
    __half* Xs = (__half*)(smc + PRJ_XS);
    __half* Ws = (__half*)(smc + PRJ_WS);
    float*  sg = (float*)(smc + PRJ_SG);

    int tid = threadIdx.x;
    int lane = tid & 31, w = tid >> 5;
    int gr = lane >> 2, cl = lane & 3;
    int wo = w * 16;

    int j0  = blockIdx.x * 128;
    int b   = j0 >> 14;
    int r0  = j0 & 16383;
    int n0p = r0 >> 4;                       // base patch (multiple of 8)
    int t   = n0p >> 8, hi = (n0p >> 4) & 15, wi0 = n0p & 15;

    // ---- load X tile coalesced (128B rows), write patch-ordered [j][c] fp16 ----
    {
        int cc = lane;                       // spatial col within 32-wide block
        int nl = cc >> 2, sw = cc & 3;
        int j  = nl*16 + (cc & 3);           // partial; sh added below
        const float* xb = x + (size_t)b*128*16384 + t*4096 + hi*256 + wi0*4;
        #pragma unroll 4
        for (int it = 0; it < 64; it++) {
            int grp = w + it*8;
            int c = grp >> 2, sh = grp & 3;
            float v = xb[(size_t)c*16384 + sh*64 + cc];
            int jj = nl*16 + sh*4 + sw;
            Xs[jj*136 + (c ^ ((jj >> 4) << 1))] = __float2half(v);
        }
        (void)j;
    }

    const float* Wp0[3] = {Wq, Wk, Wv};

    for (int proj = 0; proj < 3; proj++) {
        __syncthreads();                     // prev mma done / X visible
        const float* Wm = Wp0[proj];
        for (int e = tid; e < 16384; e += 256)
            Ws[(e >> 7)*136 + (e & 127)] = __float2half(Wm[e]);
        if (tid < 64) sg[tid] = 0.f;
        __syncthreads();

        float acc[16][4];
        #pragma unroll
        for (int nt = 0; nt < 16; nt++)
            #pragma unroll
            for (int ci = 0; ci < 4; ci++) acc[nt][ci] = 0.f;

        #pragma unroll
        for (int ks = 0; ks < 8; ks++) {
            int k0 = ks*16;
            uint32_t a0 = *(uint32_t*)&Ws[(wo+gr  )*136 + k0 + 2*cl];
            uint32_t a1 = *(uint32_t*)&Ws[(wo+gr+8)*136 + k0 + 2*cl];
            uint32_t a2 = *(uint32_t*)&Ws[(wo+gr  )*136 + k0 + 2*cl + 8];
            uint32_t a3 = *(uint32_t*)&Ws[(wo+gr+8)*136 + k0 + 2*cl + 8];
            #pragma unroll
            for (int nt = 0; nt < 16; nt++) {
                int swz = (nt >> 1) << 1;
                uint32_t b0 = *(uint32_t*)&Xs[(nt*8+gr)*136 + ((k0 + 2*cl    ) ^ swz)];
                uint32_t b1 = *(uint32_t*)&Xs[(nt*8+gr)*136 + ((k0 + 2*cl + 8) ^ swz)];
                mma_f16(acc[nt], a0, a1, a2, a3, b0, b1);
            }
        }

        // ---- epilogue ----
        // element (o = wo + gr + 8*(ci>>1), j = nt*8 + 2*cl + (ci&1))
        if (proj < 2) {
            float* pool = (proj == 0) ? g_qpool : g_kpool;
            #pragma unroll
            for (int oh = 0; oh < 2; oh++) {
                int o = wo + gr + 8*oh;
                #pragma unroll
                for (int nl = 0; nl < 8; nl++) {
                    float s = acc[2*nl][oh*2] + acc[2*nl][oh*2+1]
                            + acc[2*nl+1][oh*2] + acc[2*nl+1][oh*2+1];
                    s += __shfl_xor_sync(0xffffffffu, s, 1);
                    s += __shfl_xor_sync(0xffffffffu, s, 2);
                    if (cl == 0)
                        pool[(size_t)(b*128 + o)*1024 + n0p + nl] = s * 0.0625f;
                }
            }
        } else {
            #pragma unroll
            for (int oh = 0; oh < 2; oh++) {
                int o = wo + gr + 8*oh;
                __half* dst = g_vh + (size_t)(b*128 + o)*16384 + r0;
                #pragma unroll
                for (int nt = 0; nt < 16; nt++) {
                    __half2 h = __floats2half2_rn(acc[nt][oh*2], acc[nt][oh*2+1]);
                    *(__half2*)&dst[nt*8 + 2*cl] = h;
                }
            }
        }

        // GN stats: per-thread partials per oh, shfl-reduce over cl, smem atomics
        {
            float s0 = 0.f, q0 = 0.f, s1 = 0.f, q1 = 0.f;
            #pragma unroll
            for (int nt = 0; nt < 16; nt++) {
                float v00 = acc[nt][0], v01 = acc[nt][1];
                float v10 = acc[nt][2], v11 = acc[nt][3];
                s0 += v00 + v01; q0 += v00*v00 + v01*v01;
                s1 += v10 + v11; q1 += v10*v10 + v11*v11;
            }
            s0 += __shfl_xor_sync(0xffffffffu, s0, 1);
            s0 += __shfl_xor_sync(0xffffffffu, s0, 2);
            q0 += __shfl_xor_sync(0xffffffffu, q0, 1);
            q0 += __shfl_xor_sync(0xffffffffu, q0, 2);
            s1 += __shfl_xor_sync(0xffffffffu, s1, 1);
            s1 += __shfl_xor_sync(0xffffffffu, s1, 2);
            q1 += __shfl_xor_sync(0xffffffffu, q1, 1);
            q1 += __shfl_xor_sync(0xffffffffu, q1, 2);
            if (cl == 0) {
                int g0 = (wo + gr) >> 2, g1 = (wo + gr + 8) >> 2;
                atomicAdd(&sg[g0*2    ], s0);
                atomicAdd(&sg[g0*2 + 1], q0);
                atomicAdd(&sg[g1*2    ], s1);
                atomicAdd(&sg[g1*2 + 1], q1);
            }
        }
        __syncthreads();
        if (tid < 64)
            atomicAdd(&g_stats[((proj*B_ + b)*NH)*2 + tid], sg[tid]);
    }
}

// ---------------- kernel 2: attention, PV on mma.sync fp16 ----------------
// smem: floats [ksm 4096 | qsm 512 | tbl 6728] then half Ssm[128][72], half Vsm[64][72], sums[128]
#define AT_SSM_B  45344
#define AT_VSM_B  (AT_SSM_B + 128*72*2)
#define AT_SUM_B  (AT_VSM_B + 64*72*2)
#define AT_SMEM   (AT_SUM_B + 512)

__global__ void __launch_bounds__(256, 2)
attn_kernel(const float* __restrict__ gq_g, const float* __restrict__ gq_b,
            const float* __restrict__ gk_g, const float* __restrict__ gk_b,
            const float* __restrict__ gv_g, const float* __restrict__ gv_b,
            const float* __restrict__ rel_table,
            float* __restrict__ out) {
    extern __shared__ float smf[];
    float* ksm = smf;
    float* qsm = smf + 4096;
    float* tbl = smf + 4608;
    __half* Ssm = (__half*)((char*)smf + AT_SSM_B);   // [128][72] P fp16
    __half* Vsm = (__half*)((char*)smf + AT_VSM_B);   // [dp=64][72] V fp16
    float* sums = (float*)((char*)smf + AT_SUM_B);

    int tid  = threadIdx.x;
    int w    = tid >> 5, lane = tid & 31;
    int gr   = lane >> 2, cl = lane & 3;
    int bh   = blockIdx.x;
    int b    = bh >> 5, head = bh & 31;
    int n0   = blockIdx.y << 7;
    int c0   = head * 4;

    // GN stats finalize (inline)
    float muq, rsq, muk, rsk, muv, rsv;
    {
        float s, q;
        s = g_stats[((0*B_ + b)*NH + head)*2]; q = g_stats[((0*B_ + b)*NH + head)*2 + 1];
        muq = s*(1.f/65536.f); rsq = rsqrtf(q*(1.f/65536.f) - muq*muq + 1e-5f);
        s = g_stats[((1*B_ + b)*NH + head)*2]; q = g_stats[((1*B_ + b)*NH + head)*2 + 1];
        muk = s*(1.f/65536.f); rsk = rsqrtf(q*(1.f/65536.f) - muk*muk + 1e-5f);
        s = g_stats[((2*B_ + b)*NH + head)*2]; q = g_stats[((2*B_ + b)*NH + head)*2 + 1];
        muv = s*(1.f/65536.f); rsv = rsqrtf(q*(1.f/65536.f) - muv*muv + 1e-5f);
    }

    // normalized pooled keys [d][1024]
    for (int e = tid; e < 4096; e += 256) {
        int d = e >> 10, m = e & 1023;
        float a  = gk_g[c0 + d] * rsk;
        float bb = gk_b[c0 + d] - muk * a;
        ksm[e] = a * g_kpool[(size_t)(b*128 + c0 + d)*1024 + m] + bb;
    }
    // normalized pooled queries [q][d], 0.5 scale folded
    for (int e = tid; e < 512; e += 256) {
        int q = e >> 2, d = e & 3;
        float a  = gq_g[c0 + d] * rsq;
        float bb = gq_b[c0 + d] - muq * a;
        qsm[e] = 0.5f * (a * g_qpool[(size_t)(b*128 + c0 + d)*1024 + n0 + q] + bb);
    }
    for (int e = tid; e < TBL; e += 256) tbl[e] = rel_table[head*TBL + e];
    __syncthreads();

    int mloc = tid & 63;
    int qg   = tid >> 6;
    float psum[32];
    #pragma unroll
    for (int j = 0; j < 32; j++) psum[j] = 0.f;

    int qt = w >> 1, nh = w & 1;
    float acc[2][4][4];
    #pragma unroll
    for (int i2 = 0; i2 < 2; i2++)
        #pragma unroll
        for (int nt = 0; nt < 4; nt++)
            #pragma unroll
            for (int ci = 0; ci < 4; ci++) acc[i2][nt][ci] = 0.f;

    const __half* vb = g_vh + (size_t)(b*128 + c0) * 16384;

    #pragma unroll 1
    for (int ch = 0; ch < 16; ch++) {
        int m0 = ch << 6;

        // ---- stage V chunk: Vsm[dp][m], coalesced half2 reads ----
        #pragma unroll
        for (int it = 0; it < 8; it++) {
            int e = tid + it*256;
            int d = e >> 9, rem = e & 511;
            int m = rem >> 3, pp = rem & 7;
            __half2 h = *(const __half2*)&vb[(size_t)d*16384 + (m0 + m)*16 + pp*2];
            Vsm[(d*16 + 2*pp    )*72 + m] = __low2half(h);
            Vsm[(d*16 + 2*pp + 1)*72 + m] = __high2half(h);
        }

        // ---- scores -> exp -> Ssm (fp16) + psum (fp32) ----
        {
            int gm = m0 + mloc;
            float kv0 = ksm[gm];
            float kv1 = ksm[1024 + gm];
            float kv2 = ksm[2048 + gm];
            float kv3 = ksm[3072 + gm];
            int t2 = gm >> 8, y2 = (gm >> 4) & 15, x2 = gm & 15;
            #pragma unroll
            for (int j = 0; j < 32; j++) {
                int q = qg + 4*j;
                int n = n0 + q;
                int t1 = n >> 8, y1 = (n >> 4) & 15, x1 = n & 15;
                int idx = ((t1 - t2 + 3)*31 + (y1 - y2 + 15))*31 + (x1 - x2 + 15);
                float4 qv = *(float4*)&qsm[q*4];
                float s = qv.x*kv0 + qv.y*kv1 + qv.z*kv2 + qv.w*kv3 + tbl[idx];
                float p = __expf(s);
                psum[j] += p;
                Ssm[q*72 + mloc] = __float2half(p);
            }
        }
        __syncthreads();

        // ---- mma: O[128x64] += P[128x64] @ V[64x64], fp16 k16 ----
        #pragma unroll
        for (int ks = 0; ks < 4; ks++) {
            int k0 = ks*16;
            uint32_t a[2][4];
            #pragma unroll
            for (int i2 = 0; i2 < 2; i2++) {
                int row = qt*32 + i2*16;
                a[i2][0] = *(uint32_t*)&Ssm[(row + gr    )*72 + k0 + 2*cl];
                a[i2][1] = *(uint32_t*)&Ssm[(row + gr + 8)*72 + k0 + 2*cl];
                a[i2][2] = *(uint32_t*)&Ssm[(row + gr    )*72 + k0 + 2*cl + 8];
                a[i2][3] = *(uint32_t*)&Ssm[(row + gr + 8)*72 + k0 + 2*cl + 8];
            }
            #pragma unroll
            for (int nt = 0; nt < 4; nt++) {
                int nb = nh*32 + nt*8;
                uint32_t b0 = *(uint32_t*)&Vsm[(nb + gr)*72 + k0 + 2*cl];
                uint32_t b1 = *(uint32_t*)&Vsm[(nb + gr)*72 + k0 + 2*cl + 8];
                mma_f16(acc[0][nt], a[0][0], a[0][1], a[0][2], a[0][3], b0, b1);
                mma_f16(acc[1][nt], a[1][0], a[1][1], a[1][2], a[1][3], b0, b1);
            }
        }
        __syncthreads();
    }

    // ---- row-sum reduction ----
    #pragma unroll
    for (int j = 0; j < 32; j++) {
        float v = psum[j];
        v += __shfl_xor_sync(0xffffffffu, v, 1);
        v += __shfl_xor_sync(0xffffffffu, v, 2);
        v += __shfl_xor_sync(0xffffffffu, v, 4);
        v += __shfl_xor_sync(0xffffffffu, v, 8);
        v += __shfl_xor_sync(0xffffffffu, v, 16);
        psum[j] = v;
    }
    float* scr = (float*)Vsm;
    if (lane == 0) {
        #pragma unroll
        for (int j = 0; j < 32; j++) scr[w*32 + j] = psum[j];
    }
    __syncthreads();
    if (tid < 128) {
        int g = tid & 3, j = tid >> 2;
        sums[tid] = scr[(2*g)*32 + j] + scr[(2*g + 1)*32 + j];
    }
    __syncthreads();

    // ---- epilogue: normalize + v-affine -> stage (reuse float region) ----
    float av[4], bv[4];
    #pragma unroll
    for (int d = 0; d < 4; d++) {
        av[d] = gv_g[c0 + d] * rsv;
        bv[d] = gv_b[c0 + d] - muv * av[d];
    }
    float* stage = smf;     // [128][68]
    {
        float invl[2][2];
        #pragma unroll
        for (int i2 = 0; i2 < 2; i2++)
            #pragma unroll
            for (int h8 = 0; h8 < 2; h8++)
                invl[i2][h8] = 1.f / sums[qt*32 + i2*16 + gr + h8*8];
        #pragma unroll
        for (int i2 = 0; i2 < 2; i2++)
            #pragma unroll
            for (int nt = 0; nt < 4; nt++)
                #pragma unroll
                for (int ci = 0; ci < 4; ci++) {
                    int h8  = (ci >> 1) & 1;
                    int row = qt*32 + i2*16 + gr + h8*8;
                    int col = nh*32 + nt*8 + cl*2 + (ci & 1);
                    int d   = col >> 4;
                    stage[row*68 + col] = av[d]*(acc[i2][nt][ci]*invl[i2][h8]) + bv[d];
                }
    }
    __syncthreads();

    // ---- coalesced global write ----
    int t   = n0 >> 8;
    int hi0 = (n0 >> 4) & 15;
    #pragma unroll
    for (int it = 0; it < 32; it++) {
        int e = tid + it*256;
        int rr = e >> 6, cc = e & 63;
        int d = rr >> 5, hl = (rr >> 2) & 7, sh = rr & 3;
        int q = hl*16 + (cc >> 2);
        int dp = d*16 + sh*4 + (cc & 3);
        out[(size_t)(b*128 + c0 + d)*16384 + t*4096 + ((hi0 + hl)*4 + sh)*64 + cc]
            = stage[q*68 + dp];
    }
}

// ---------------- launcher ----------------
extern "C" void kernel_launch(void* const* d_in, const int* in_sizes, int n_in,
                              void* d_out, int out_size) {
    (void)in_sizes; (void)n_in; (void)out_size;
    const float* x    = (const float*)d_in[0];
    const float* Wq   = (const float*)d_in[1];
    const float* Wk   = (const float*)d_in[2];
    const float* Wv   = (const float*)d_in[3];
    const float* gq_g = (const float*)d_in[4];
    const float* gq_b = (const float*)d_in[5];
    const float* gk_g = (const float*)d_in[6];
    const float* gk_b = (const float*)d_in[7];
    const float* gv_g = (const float*)d_in[8];
    const float* gv_b = (const float*)d_in[9];
    const float* rel_table = (const float*)d_in[10];
    float* out = (float*)d_out;

    cudaFuncSetAttribute(proj_kernel, cudaFuncAttributeMaxDynamicSharedMemorySize, PRJ_SMEM);
    cudaFuncSetAttribute(attn_kernel, cudaFuncAttributeMaxDynamicSharedMemorySize, AT_SMEM);

    zero_stats_kernel<<<1, 512>>>();
    proj_kernel<<<256, 256, PRJ_SMEM>>>(x, Wq, Wk, Wv);
    attn_kernel<<<dim3(64, 8), 256, AT_SMEM>>>(gq_g, gq_b, gk_g, gk_b,
                                               gv_g, gv_b, rel_table, out);
}

// round 6
// speedup vs baseline: 9.3828x; 1.4524x over previous
#include <cuda_runtime.h>
#include <cuda_fp16.h>
#include <math.h>
#include <stdint.h>

// Problem constants
#define B_   2
#define NH   32
#define TBL  6727
#define LOG2E 1.44269504088896340736f

// ---------------- scratch ----------------
__device__ __half g_vh[B_*128*16384];      // projected v, fp16, patch layout [b][c][n*16+p]
__device__ float g_qpool[B_*128*1024];
__device__ float g_kpool[B_*128*1024];
__device__ float g_part[3*B_*NH*2*128];    // per-CTA GN stat partials

// ---------------- helpers ----------------
__device__ __forceinline__ void mma_f16(float c[4], uint32_t a0, uint32_t a1,
                                        uint32_t a2, uint32_t a3,
                                        uint32_t b0, uint32_t b1) {
    asm volatile(
        "mma.sync.aligned.m16n8k16.row.col.f32.f16.f16.f32 "
        "{%0,%1,%2,%3}, {%4,%5,%6,%7}, {%8,%9}, {%0,%1,%2,%3};"
        : "+f"(c[0]), "+f"(c[1]), "+f"(c[2]), "+f"(c[3])
        : "r"(a0), "r"(a1), "r"(a2), "r"(a3), "r"(b0), "r"(b1));
}
__device__ __forceinline__ void ldsm4(uint32_t& r0, uint32_t& r1, uint32_t& r2, uint32_t& r3,
                                      uint32_t addr) {
    asm volatile("ldmatrix.sync.aligned.m8n8.x4.shared.b16 {%0,%1,%2,%3}, [%4];"
                 : "=r"(r0), "=r"(r1), "=r"(r2), "=r"(r3) : "r"(addr));
}
__device__ __forceinline__ void ldsm4t(uint32_t& r0, uint32_t& r1, uint32_t& r2, uint32_t& r3,
                                       uint32_t addr) {
    asm volatile("ldmatrix.sync.aligned.m8n8.x4.trans.shared.b16 {%0,%1,%2,%3}, [%4];"
                 : "=r"(r0), "=r"(r1), "=r"(r2), "=r"(r3) : "r"(addr));
}
__device__ __forceinline__ float ex2f(float x) {
    float y;
    asm("ex2.approx.ftz.f32 %0, %1;" : "=f"(y) : "f"(x));
    return y;
}

// ---------------- kernel 1: fused projections + pooling + GN partials + v store ----------------
#define PRJ_XS 0                 // half [j=128][136], col swizz c^(2*(j>>4))
#define PRJ_WS 34816             // half [o=128][136]
#define PRJ_SG 69632             // float [32][2]
#define PRJ_SMEM (69632 + 256)

__global__ void __launch_bounds__(256, 2)
proj_kernel(const float* __restrict__ x,
            const float* __restrict__ Wq,
            const float* __restrict__ Wk,
            const float* __restrict__ Wv) {
    extern __shared__ char smc[];
    __half* Xs = (__half*)(smc + PRJ_XS);
    __half* Ws = (__half*)(smc + PRJ_WS);
    float*  sg = (float*)(smc + PRJ_SG);

    int tid = threadIdx.x;
    int lane = tid & 31, w = tid >> 5;
    int gr = lane >> 2, cl = lane & 3;
    int wo = w * 16;

    int j0  = blockIdx.x * 128;
    int b   = j0 >> 14;
    int local = blockIdx.x & 127;
    int r0  = j0 & 16383;
    int n0p = r0 >> 4;
    int t   = n0p >> 8, hi = (n0p >> 4) & 15, wi0 = n0p & 15;

    // ---- load X tile coalesced, write patch-ordered [j][c] fp16 (paired c -> half2) ----
    {
        int cc = lane;
        int nl = cc >> 2, sw = cc & 3;
        const float* xb = x + (size_t)b*128*16384 + t*4096 + hi*256 + wi0*4;
        #pragma unroll 4
        for (int it = 0; it < 32; it++) {
            int grp = w + it*8;
            int cp = grp >> 2, sh = grp & 3;
            int c0 = cp * 2;
            float v0 = xb[(size_t)c0*16384 + sh*64 + cc];
            float v1 = xb[(size_t)(c0+1)*16384 + sh*64 + cc];
            int jj = nl*16 + sh*4 + sw;
            *(__half2*)&Xs[jj*136 + (c0 ^ ((jj >> 4) << 1))] = __floats2half2_rn(v0, v1);
        }
    }

    const float* Wp0[3] = {Wq, Wk, Wv};

    for (int proj = 0; proj < 3; proj++) {
        __syncthreads();
        const float* Wm = Wp0[proj];
        #pragma unroll
        for (int it = 0; it < 16; it++) {
            int e = tid + it*256;             // float4 index
            int o = e >> 5, col = (e & 31) * 4;
            float4 f4 = ((const float4*)Wm)[e];
            *(__half2*)&Ws[o*136 + col]     = __floats2half2_rn(f4.x, f4.y);
            *(__half2*)&Ws[o*136 + col + 2] = __floats2half2_rn(f4.z, f4.w);
        }
        if (tid < 64) sg[tid] = 0.f;
        __syncthreads();

        float acc[16][4];
        #pragma unroll
        for (int nt = 0; nt < 16; nt++)
            #pragma unroll
            for (int ci = 0; ci < 4; ci++) acc[nt][ci] = 0.f;

        #pragma unroll
        for (int ks = 0; ks < 8; ks++) {
            int k0 = ks*16;
            uint32_t a0 = *(uint32_t*)&Ws[(wo+gr  )*136 + k0 + 2*cl];
            uint32_t a1 = *(uint32_t*)&Ws[(wo+gr+8)*136 + k0 + 2*cl];
            uint32_t a2 = *(uint32_t*)&Ws[(wo+gr  )*136 + k0 + 2*cl + 8];
            uint32_t a3 = *(uint32_t*)&Ws[(wo+gr+8)*136 + k0 + 2*cl + 8];
            #pragma unroll
            for (int nt = 0; nt < 16; nt++) {
                int swz = (nt >> 1) << 1;
                uint32_t b0 = *(uint32_t*)&Xs[(nt*8+gr)*136 + ((k0 + 2*cl    ) ^ swz)];
                uint32_t b1 = *(uint32_t*)&Xs[(nt*8+gr)*136 + ((k0 + 2*cl + 8) ^ swz)];
                mma_f16(acc[nt], a0, a1, a2, a3, b0, b1);
            }
        }

        // ---- epilogue: pool q/k or store v ----
        if (proj < 2) {
            float* pool = (proj == 0) ? g_qpool : g_kpool;
            #pragma unroll
            for (int oh = 0; oh < 2; oh++) {
                int o = wo + gr + 8*oh;
                #pragma unroll
                for (int nl = 0; nl < 8; nl++) {
                    float s = acc[2*nl][oh*2] + acc[2*nl][oh*2+1]
                            + acc[2*nl+1][oh*2] + acc[2*nl+1][oh*2+1];
                    s += __shfl_xor_sync(0xffffffffu, s, 1);
                    s += __shfl_xor_sync(0xffffffffu, s, 2);
                    if (cl == 0)
                        pool[(size_t)(b*128 + o)*1024 + n0p + nl] = s * 0.0625f;
                }
            }
        } else {
            #pragma unroll
            for (int oh = 0; oh < 2; oh++) {
                int o = wo + gr + 8*oh;
                __half* dst = g_vh + (size_t)(b*128 + o)*16384 + r0;
                #pragma unroll
                for (int nt = 0; nt < 16; nt++) {
                    __half2 h = __floats2half2_rn(acc[nt][oh*2], acc[nt][oh*2+1]);
                    *(__half2*)&dst[nt*8 + 2*cl] = h;
                }
            }
        }

        // GN stats partials
        {
            float s0 = 0.f, q0 = 0.f, s1 = 0.f, q1 = 0.f;
            #pragma unroll
            for (int nt = 0; nt < 16; nt++) {
                float v00 = acc[nt][0], v01 = acc[nt][1];
                float v10 = acc[nt][2], v11 = acc[nt][3];
                s0 += v00 + v01; q0 += v00*v00 + v01*v01;
                s1 += v10 + v11; q1 += v10*v10 + v11*v11;
            }
            s0 += __shfl_xor_sync(0xffffffffu, s0, 1);
            s0 += __shfl_xor_sync(0xffffffffu, s0, 2);
            q0 += __shfl_xor_sync(0xffffffffu, q0, 1);
            q0 += __shfl_xor_sync(0xffffffffu, q0, 2);
            s1 += __shfl_xor_sync(0xffffffffu, s1, 1);
            s1 += __shfl_xor_sync(0xffffffffu, s1, 2);
            q1 += __shfl_xor_sync(0xffffffffu, q1, 1);
            q1 += __shfl_xor_sync(0xffffffffu, q1, 2);
            if (cl == 0) {
                int g0 = (wo + gr) >> 2, g1 = (wo + gr + 8) >> 2;
                atomicAdd(&sg[g0*2    ], s0);
                atomicAdd(&sg[g0*2 + 1], q0);
                atomicAdd(&sg[g1*2    ], s1);
                atomicAdd(&sg[g1*2 + 1], q1);
            }
        }
        __syncthreads();
        if (tid < 64)
            g_part[(((proj*B_ + b)*NH + (tid >> 1))*2 + (tid & 1))*128 + local] = sg[tid];
    }
}

// ---------------- kernel 2: attention ----------------
// float offsets
#define F_KSM   0        // [4][1024]
#define F_QSM   4096     // [128][4]  (0.5*log2e folded)
#define F_TBL   4608     // 6728 (×log2e)
#define F_KEYQ  11336    // int [128]  (+3363 folded)
#define F_KEYM  11464    // int [1024]
#define F_SUMS  12488    // [128]
#define F_STAT  12616    // [8]
#define AT_SSM_B  50496  // half [128][72]  (P)
#define AT_VSM_B  68928  // half [64][72]   (V chunk, [m][dp])
#define AT_SMEM   78144

__global__ void __launch_bounds__(256, 2)
attn_kernel(const float* __restrict__ gq_g, const float* __restrict__ gq_b,
            const float* __restrict__ gk_g, const float* __restrict__ gk_b,
            const float* __restrict__ gv_g, const float* __restrict__ gv_b,
            const float* __restrict__ rel_table,
            float* __restrict__ out) {
    extern __shared__ float smf[];
    float* ksm  = smf + F_KSM;
    float* qsm  = smf + F_QSM;
    float* tbl  = smf + F_TBL;
    int*   keyq = (int*)(smf + F_KEYQ);
    int*   keym = (int*)(smf + F_KEYM);
    float* sums = smf + F_SUMS;
    float* st6  = smf + F_STAT;
    __half* Ssm = (__half*)((char*)smf + AT_SSM_B);
    __half* Vsm = (__half*)((char*)smf + AT_VSM_B);

    int tid  = threadIdx.x;
    int w    = tid >> 5, lane = tid & 31;
    int gr   = lane >> 2, cl = lane & 3;
    int bh   = blockIdx.x;
    int b    = bh >> 5, head = bh & 31;
    int n0   = blockIdx.y << 7;
    int c0   = head * 4;

    // ---- phase 1: stat-partial reduce + tbl/key staging ----
    if (w < 6) {
        int pr = w >> 1, s = w & 1;
        const float* gp = g_part + (size_t)(((pr*B_ + b)*NH + head)*2 + s)*128;
        float4 v = ((const float4*)gp)[lane];
        float tt = v.x + v.y + v.z + v.w;
        tt += __shfl_xor_sync(0xffffffffu, tt, 1);
        tt += __shfl_xor_sync(0xffffffffu, tt, 2);
        tt += __shfl_xor_sync(0xffffffffu, tt, 4);
        tt += __shfl_xor_sync(0xffffffffu, tt, 8);
        tt += __shfl_xor_sync(0xffffffffu, tt, 16);
        if (lane == 0) st6[pr*2 + s] = tt;
    }
    for (int e = tid; e < TBL; e += 256) tbl[e] = rel_table[head*TBL + e] * LOG2E;
    for (int e = tid; e < 1024; e += 256) {
        int t2 = e >> 8, y2 = (e >> 4) & 15, x2 = e & 15;
        keym[e] = t2*961 + y2*31 + x2;
    }
    if (tid < 128) {
        int n = n0 + tid;
        int t1 = n >> 8, y1 = (n >> 4) & 15, x1 = n & 15;
        keyq[tid] = t1*961 + y1*31 + x1 + 3363;
    }
    __syncthreads();

    // ---- phase 2: normalized pooled k/q staging ----
    float muq, rsq, muk, rsk, muv, rsv;
    {
        muq = st6[0]*(1.f/65536.f); rsq = rsqrtf(st6[1]*(1.f/65536.f) - muq*muq + 1e-5f);
        muk = st6[2]*(1.f/65536.f); rsk = rsqrtf(st6[3]*(1.f/65536.f) - muk*muk + 1e-5f);
        muv = st6[4]*(1.f/65536.f); rsv = rsqrtf(st6[5]*(1.f/65536.f) - muv*muv + 1e-5f);
    }
    for (int e = tid; e < 4096; e += 256) {
        int d = e >> 10, m = e & 1023;
        float a  = gk_g[c0 + d] * rsk;
        float bb = gk_b[c0 + d] - muk * a;
        ksm[e] = a * g_kpool[(size_t)(b*128 + c0 + d)*1024 + m] + bb;
    }
    for (int e = tid; e < 512; e += 256) {
        int q = e >> 2, d = e & 3;
        float a  = gq_g[c0 + d] * rsq;
        float bb = gq_b[c0 + d] - muq * a;
        qsm[e] = (0.5f*LOG2E) * (a * g_qpool[(size_t)(b*128 + c0 + d)*1024 + n0 + q] + bb);
    }
    __syncthreads();

    float psum[16];
    #pragma unroll
    for (int j = 0; j < 16; j++) psum[j] = 0.f;

    int qt = w >> 1, nh = w & 1;
    float acc[2][4][4];
    #pragma unroll
    for (int i2 = 0; i2 < 2; i2++)
        #pragma unroll
        for (int nt = 0; nt < 4; nt++)
            #pragma unroll
            for (int ci = 0; ci < 4; ci++) acc[i2][nt][ci] = 0.f;

    const __half* vb = g_vh + (size_t)(b*128 + c0) * 16384;
    uint32_t ssm_a = (uint32_t)__cvta_generic_to_shared(Ssm);
    uint32_t vsm_a = (uint32_t)__cvta_generic_to_shared(Vsm);

    #pragma unroll 1
    for (int ch = 0; ch < 16; ch++) {
        int m0 = ch << 6;

        // ---- stage V chunk: Vsm[m][dp], 16B vector copies ----
        #pragma unroll
        for (int it = 0; it < 2; it++) {
            int e = tid + it*256;            // 8-half chunk index
            int m = e >> 3, seg = e & 7;
            int d = seg >> 1, p8 = (seg & 1) * 8;
            float4 vv = *(const float4*)&vb[(size_t)d*16384 + (m0 + m)*16 + p8];
            *(float4*)&Vsm[m*72 + seg*8] = vv;
        }

        // ---- scores -> exp -> Ssm (half2) + psum ----
        {
            int gm = m0 + 2*lane;
            float2 k0v = *(float2*)&ksm[gm];
            float2 k1v = *(float2*)&ksm[1024 + gm];
            float2 k2v = *(float2*)&ksm[2048 + gm];
            float2 k3v = *(float2*)&ksm[3072 + gm];
            int2   km  = *(int2*)&keym[gm];
            #pragma unroll
            for (int j = 0; j < 16; j++) {
                int q = w + 8*j;
                float4 qv = *(float4*)&qsm[q*4];
                int kq = keyq[q];
                float b0 = tbl[kq - km.x];
                float b1 = tbl[kq - km.y];
                float s0 = fmaf(qv.x,k0v.x, fmaf(qv.y,k1v.x, fmaf(qv.z,k2v.x, fmaf(qv.w,k3v.x, b0))));
                float s1 = fmaf(qv.x,k0v.y, fmaf(qv.y,k1v.y, fmaf(qv.z,k2v.y, fmaf(qv.w,k3v.y, b1))));
                float p0 = ex2f(s0), p1 = ex2f(s1);
                psum[j] += p0 + p1;
                *(__half2*)&Ssm[q*72 + 2*lane] = __floats2half2_rn(p0, p1);
            }
        }
        __syncthreads();

        // ---- mma via ldmatrix ----
        #pragma unroll
        for (int ks = 0; ks < 4; ks++) {
            int k0 = ks*16;
            uint32_t a[2][4], bb[2][4];
            #pragma unroll
            for (int i2 = 0; i2 < 2; i2++) {
                uint32_t adr = ssm_a +
                    ((qt*32 + i2*16 + (lane & 15))*72 + k0 + ((lane >> 4) << 3))*2;
                ldsm4(a[i2][0], a[i2][1], a[i2][2], a[i2][3], adr);
            }
            #pragma unroll
            for (int np = 0; np < 2; np++) {
                uint32_t adr = vsm_a +
                    ((k0 + (lane & 15))*72 + nh*32 + np*16 + ((lane >> 4) << 3))*2;
                ldsm4t(bb[np][0], bb[np][1], bb[np][2], bb[np][3], adr);
            }
            #pragma unroll
            for (int i2 = 0; i2 < 2; i2++)
                #pragma unroll
                for (int nt = 0; nt < 4; nt++)
                    mma_f16(acc[i2][nt], a[i2][0], a[i2][1], a[i2][2], a[i2][3],
                            bb[nt >> 1][(nt & 1)*2], bb[nt >> 1][(nt & 1)*2 + 1]);
        }
        __syncthreads();
    }

    // ---- row sums: per-warp full reduce (warp w owns q ≡ w mod 8) ----
    #pragma unroll
    for (int j = 0; j < 16; j++) {
        float v = psum[j];
        v += __shfl_xor_sync(0xffffffffu, v, 1);
        v += __shfl_xor_sync(0xffffffffu, v, 2);
        v += __shfl_xor_sync(0xffffffffu, v, 4);
        v += __shfl_xor_sync(0xffffffffu, v, 8);
        v += __shfl_xor_sync(0xffffffffu, v, 16);
        if (lane == 0) sums[w + 8*j] = v;
    }
    __syncthreads();

    // ---- epilogue: normalize + v-affine -> stage ----
    float av[4], bv[4];
    #pragma unroll
    for (int d = 0; d < 4; d++) {
        av[d] = gv_g[c0 + d] * rsv;
        bv[d] = gv_b[c0 + d] - muv * av[d];
    }
    float* stage = smf;     // [128][68]
    {
        float invl[2][2];
        #pragma unroll
        for (int i2 = 0; i2 < 2; i2++)
            #pragma unroll
            for (int h8 = 0; h8 < 2; h8++)
                invl[i2][h8] = 1.f / sums[qt*32 + i2*16 + gr + h8*8];
        #pragma unroll
        for (int i2 = 0; i2 < 2; i2++)
            #pragma unroll
            for (int nt = 0; nt < 4; nt++)
                #pragma unroll
                for (int ci = 0; ci < 4; ci++) {
                    int h8  = (ci >> 1) & 1;
                    int row = qt*32 + i2*16 + gr + h8*8;
                    int col = nh*32 + nt*8 + cl*2 + (ci & 1);
                    int d   = col >> 4;
                    stage[row*68 + col] = av[d]*(acc[i2][nt][ci]*invl[i2][h8]) + bv[d];
                }
    }
    __syncthreads();

    // ---- coalesced global write ----
    int t   = n0 >> 8;
    int hi0 = (n0 >> 4) & 15;
    #pragma unroll
    for (int it = 0; it < 32; it++) {
        int e = tid + it*256;
        int rr = e >> 6, cc = e & 63;
        int d = rr >> 5, hl = (rr >> 2) & 7, sh = rr & 3;
        int q = hl*16 + (cc >> 2);
        int dp = d*16 + sh*4 + (cc & 3);
        out[(size_t)(b*128 + c0 + d)*16384 + t*4096 + ((hi0 + hl)*4 + sh)*64 + cc]
            = stage[q*68 + dp];
    }
}

// ---------------- launcher ----------------
extern "C" void kernel_launch(void* const* d_in, const int* in_sizes, int n_in,
                              void* d_out, int out_size) {
    (void)in_sizes; (void)n_in; (void)out_size;
    const float* x    = (const float*)d_in[0];
    const float* Wq   = (const float*)d_in[1];
    const float* Wk   = (const float*)d_in[2];
    const float* Wv   = (const float*)d_in[3];
    const float* gq_g = (const float*)d_in[4];
    const float* gq_b = (const float*)d_in[5];
    const float* gk_g = (const float*)d_in[6];
    const float* gk_b = (const float*)d_in[7];
    const float* gv_g = (const float*)d_in[8];
    const float* gv_b = (const float*)d_in[9];
    const float* rel_table = (const float*)d_in[10];
    float* out = (float*)d_out;

    cudaFuncSetAttribute(proj_kernel, cudaFuncAttributeMaxDynamicSharedMemorySize, PRJ_SMEM);
    cudaFuncSetAttribute(attn_kernel, cudaFuncAttributeMaxDynamicSharedMemorySize, AT_SMEM);

    proj_kernel<<<256, 256, PRJ_SMEM>>>(x, Wq, Wk, Wv);
    attn_kernel<<<dim3(64, 8), 256, AT_SMEM>>>(gq_g, gq_b, gk_g, gk_b,
                                               gv_g, gv_b, rel_table, out);
}

// round 12
// speedup vs baseline: 11.9914x; 1.2780x over previous
#include <cuda_runtime.h>
#include <cuda_fp16.h>
#include <math.h>
#include <stdint.h>

// Problem constants
#define B_   2
#define NH   32
#define TBL  6727
#define LOG2E 1.44269504088896340736f

// ---------------- scratch ----------------
__device__ __half g_vh[B_*128*16384];      // projected v, fp16, patch layout [b][c][n*16+p]
__device__ float g_qpool[B_*128*1024];
__device__ float g_kpool[B_*128*1024];
__device__ float g_part[3*B_*NH*2*128];    // per-CTA GN stat partials

// ---------------- helpers ----------------
__device__ __forceinline__ void mma_f16(float c[4], uint32_t a0, uint32_t a1,
                                        uint32_t a2, uint32_t a3,
                                        uint32_t b0, uint32_t b1) {
    asm volatile(
        "mma.sync.aligned.m16n8k16.row.col.f32.f16.f16.f32 "
        "{%0,%1,%2,%3}, {%4,%5,%6,%7}, {%8,%9}, {%0,%1,%2,%3};"
        : "+f"(c[0]), "+f"(c[1]), "+f"(c[2]), "+f"(c[3])
        : "r"(a0), "r"(a1), "r"(a2), "r"(a3), "r"(b0), "r"(b1));
}
__device__ __forceinline__ void ldsm4t(uint32_t& r0, uint32_t& r1, uint32_t& r2, uint32_t& r3,
                                       uint32_t addr) {
    asm volatile("ldmatrix.sync.aligned.m8n8.x4.trans.shared.b16 {%0,%1,%2,%3}, [%4];"
                 : "=r"(r0), "=r"(r1), "=r"(r2), "=r"(r3) : "r"(addr));
}
__device__ __forceinline__ float ex2f(float x) {
    float y;
    asm("ex2.approx.ftz.f32 %0, %1;" : "=f"(y) : "f"(x));
    return y;
}
__device__ __forceinline__ uint32_t smem_u32(const void* p) {
    uint32_t a;
    asm("{ .reg .u64 t; cvta.to.shared.u64 t, %1; cvt.u32.u64 %0, t; }" : "=r"(a) : "l"(p));
    return a;
}
__device__ __forceinline__ void cpasync16(uint32_t dst, const void* src) {
    asm volatile("cp.async.cg.shared.global [%0], [%1], 16;" :: "r"(dst), "l"(src));
}
#define CP_COMMIT() asm volatile("cp.async.commit_group;" ::: "memory")
#define CP_WAIT1()  asm volatile("cp.async.wait_group 1;" ::: "memory")

// ---------------- kernel 1: fused projections + pooling + GN partials + v store ----------------
#define PRJ_XS 0                 // half [j=128][136], col swizz c^(2*(j>>4))
#define PRJ_WS 34816             // half [o=128][136]
#define PRJ_SG 69632             // float [32][2]
#define PRJ_SMEM (69632 + 256)

__global__ void __launch_bounds__(256, 2)
proj_kernel(const float* __restrict__ x,
            const float* __restrict__ Wq,
            const float* __restrict__ Wk,
            const float* __restrict__ Wv) {
    extern __shared__ char smc[];
    __half* Xs = (__half*)(smc + PRJ_XS);
    __half* Ws = (__half*)(smc + PRJ_WS);
    float*  sg = (float*)(smc + PRJ_SG);

    int tid = threadIdx.x;
    int lane = tid & 31, w = tid >> 5;
    int gr = lane >> 2, cl = lane & 3;
    int wo = w * 16;

    int j0  = blockIdx.x * 128;
    int b   = j0 >> 14;
    int local = blockIdx.x & 127;
    int r0  = j0 & 16383;
    int n0p = r0 >> 4;
    int t   = n0p >> 8, hi = (n0p >> 4) & 15, wi0 = n0p & 15;

    // ---- load X tile coalesced, write patch-ordered [j][c] fp16 (paired c -> half2) ----
    {
        int cc = lane;
        int nl = cc >> 2, sw = cc & 3;
        const float* xb = x + (size_t)b*128*16384 + t*4096 + hi*256 + wi0*4;
        #pragma unroll 4
        for (int it = 0; it < 32; it++) {
            int grp = w + it*8;
            int cp = grp >> 2, sh = grp & 3;
            int c0 = cp * 2;
            float v0 = xb[(size_t)c0*16384 + sh*64 + cc];
            float v1 = xb[(size_t)(c0+1)*16384 + sh*64 + cc];
            int jj = nl*16 + sh*4 + sw;
            *(__half2*)&Xs[jj*136 + (c0 ^ ((jj >> 4) << 1))] = __floats2half2_rn(v0, v1);
        }
    }

    const float* Wp0[3] = {Wq, Wk, Wv};

    for (int proj = 0; proj < 3; proj++) {
        __syncthreads();
        const float* Wm = Wp0[proj];
        #pragma unroll
        for (int it = 0; it < 16; it++) {
            int e = tid + it*256;             // float4 index
            int o = e >> 5, col = (e & 31) * 4;
            float4 f4 = ((const float4*)Wm)[e];
            *(__half2*)&Ws[o*136 + col]     = __floats2half2_rn(f4.x, f4.y);
            *(__half2*)&Ws[o*136 + col + 2] = __floats2half2_rn(f4.z, f4.w);
        }
        if (tid < 64) sg[tid] = 0.f;
        __syncthreads();

        float acc[16][4];
        #pragma unroll
        for (int nt = 0; nt < 16; nt++)
            #pragma unroll
            for (int ci = 0; ci < 4; ci++) acc[nt][ci] = 0.f;

        #pragma unroll
        for (int ks = 0; ks < 8; ks++) {
            int k0 = ks*16;
            uint32_t a0 = *(uint32_t*)&Ws[(wo+gr  )*136 + k0 + 2*cl];
            uint32_t a1 = *(uint32_t*)&Ws[(wo+gr+8)*136 + k0 + 2*cl];
            uint32_t a2 = *(uint32_t*)&Ws[(wo+gr  )*136 + k0 + 2*cl + 8];
            uint32_t a3 = *(uint32_t*)&Ws[(wo+gr+8)*136 + k0 + 2*cl + 8];
            #pragma unroll
            for (int nt = 0; nt < 16; nt++) {
                int swz = (nt >> 1) << 1;
                uint32_t b0 = *(uint32_t*)&Xs[(nt*8+gr)*136 + ((k0 + 2*cl    ) ^ swz)];
                uint32_t b1 = *(uint32_t*)&Xs[(nt*8+gr)*136 + ((k0 + 2*cl + 8) ^ swz)];
                mma_f16(acc[nt], a0, a1, a2, a3, b0, b1);
            }
        }

        // ---- epilogue: pool q/k or store v ----
        if (proj < 2) {
            float* pool = (proj == 0) ? g_qpool : g_kpool;
            #pragma unroll
            for (int oh = 0; oh < 2; oh++) {
                int o = wo + gr + 8*oh;
                #pragma unroll
                for (int nl = 0; nl < 8; nl++) {
                    float s = acc[2*nl][oh*2] + acc[2*nl][oh*2+1]
                            + acc[2*nl+1][oh*2] + acc[2*nl+1][oh*2+1];
                    s += __shfl_xor_sync(0xffffffffu, s, 1);
                    s += __shfl_xor_sync(0xffffffffu, s, 2);
                    if (cl == 0)
                        pool[(size_t)(b*128 + o)*1024 + n0p + nl] = s * 0.0625f;
                }
            }
        } else {
            #pragma unroll
            for (int oh = 0; oh < 2; oh++) {
                int o = wo + gr + 8*oh;
                __half* dst = g_vh + (size_t)(b*128 + o)*16384 + r0;
                #pragma unroll
                for (int nt = 0; nt < 16; nt++) {
                    __half2 h = __floats2half2_rn(acc[nt][oh*2], acc[nt][oh*2+1]);
                    *(__half2*)&dst[nt*8 + 2*cl] = h;
                }
            }
        }

        // GN stats partials
        {
            float s0 = 0.f, q0 = 0.f, s1 = 0.f, q1 = 0.f;
            #pragma unroll
            for (int nt = 0; nt < 16; nt++) {
                float v00 = acc[nt][0], v01 = acc[nt][1];
                float v10 = acc[nt][2], v11 = acc[nt][3];
                s0 += v00 + v01; q0 += v00*v00 + v01*v01;
                s1 += v10 + v11; q1 += v10*v10 + v11*v11;
            }
            s0 += __shfl_xor_sync(0xffffffffu, s0, 1);
            s0 += __shfl_xor_sync(0xffffffffu, s0, 2);
            q0 += __shfl_xor_sync(0xffffffffu, q0, 1);
            q0 += __shfl_xor_sync(0xffffffffu, q0, 2);
            s1 += __shfl_xor_sync(0xffffffffu, s1, 1);
            s1 += __shfl_xor_sync(0xffffffffu, s1, 2);
            q1 += __shfl_xor_sync(0xffffffffu, q1, 1);
            q1 += __shfl_xor_sync(0xffffffffu, q1, 2);
            if (cl == 0) {
                int g0 = (wo + gr) >> 2, g1 = (wo + gr + 8) >> 2;
                atomicAdd(&sg[g0*2    ], s0);
                atomicAdd(&sg[g0*2 + 1], q0);
                atomicAdd(&sg[g1*2    ], s1);
                atomicAdd(&sg[g1*2 + 1], q1);
            }
        }
        __syncthreads();
        if (tid < 64)
            g_part[(((proj*B_ + b)*NH + (tid >> 1))*2 + (tid & 1))*128 + local] = sg[tid];
    }
}

// ---------------- kernel 2: attention (register-resident P fragments) ----------------
// byte offsets
#define A2_KSM   0        // float4 ksm4[1024]  -> 16384
#define A2_TBL   16384    // half  tbl16[6728]  -> 29840
#define A2_KEYM  29840    // short keym[1024]   -> 31888
#define A2_ST6   31888    // float st6[8]       -> 31920
#define A2_VSM   35712    // half  V[3][64][72] -> 63360   (stage region [0,34816) reused)
#define A2_SMEM  63360

__global__ void __launch_bounds__(256, 3)
attn_kernel(const float* __restrict__ gq_g, const float* __restrict__ gq_b,
            const float* __restrict__ gk_g, const float* __restrict__ gk_b,
            const float* __restrict__ gv_g, const float* __restrict__ gv_b,
            const float* __restrict__ rel_table,
            float* __restrict__ out) {
    extern __shared__ char smc[];
    float*  ksmf  = (float*)(smc + A2_KSM);
    float4* ksm4  = (float4*)(smc + A2_KSM);
    __half* tbl16 = (__half*)(smc + A2_TBL);
    short*  keym  = (short*)(smc + A2_KEYM);
    float*  st6   = (float*)(smc + A2_ST6);
    uint32_t sbase = smem_u32(smc);
    uint32_t vsm_a = sbase + A2_VSM;

    int tid  = threadIdx.x;
    int w    = tid >> 5, lane = tid & 31;
    int gr   = lane >> 2, cl = lane & 3;
    int bh   = blockIdx.x;
    int b    = bh >> 5, head = bh & 31;
    int n0   = blockIdx.y << 7;
    int c0   = head * 4;

    // ---- P0: stat-partial reduce + tbl(fp16) + keym staging ----
    if (w < 6) {
        int pr = w >> 1, s = w & 1;
        const float* gp = g_part + (size_t)(((pr*B_ + b)*NH + head)*2 + s)*128;
        float4 v = ((const float4*)gp)[lane];
        float tt = v.x + v.y + v.z + v.w;
        tt += __shfl_xor_sync(0xffffffffu, tt, 1);
        tt += __shfl_xor_sync(0xffffffffu, tt, 2);
        tt += __shfl_xor_sync(0xffffffffu, tt, 4);
        tt += __shfl_xor_sync(0xffffffffu, tt, 8);
        tt += __shfl_xor_sync(0xffffffffu, tt, 16);
        if (lane == 0) st6[pr*2 + s] = tt;
    }
    for (int e = tid; e < TBL; e += 256) tbl16[e] = __float2half(rel_table[head*TBL + e] * LOG2E);
    for (int e = tid; e < 1024; e += 256) {
        int t2 = e >> 8, y2 = (e >> 4) & 15, x2 = e & 15;
        keym[e] = (short)(t2*961 + y2*31 + x2);
    }
    __syncthreads();

    // ---- P1: GN constants, ksm staging, q regs, V(0) prefetch ----
    float muq = st6[0]*(1.f/65536.f), rsq = rsqrtf(st6[1]*(1.f/65536.f) - muq*muq + 1e-5f);
    float muk = st6[2]*(1.f/65536.f), rsk = rsqrtf(st6[3]*(1.f/65536.f) - muk*muk + 1e-5f);
    float muv = st6[4]*(1.f/65536.f), rsv = rsqrtf(st6[5]*(1.f/65536.f) - muv*muv + 1e-5f);

    #pragma unroll
    for (int it = 0; it < 16; it++) {
        int d = it >> 2;
        int m = tid + (it & 3)*256;
        float a  = gk_g[c0 + d] * rsk;
        float bb = gk_b[c0 + d] - muk * a;
        ksmf[m*4 + d] = a * g_kpool[(size_t)(b*128 + c0 + d)*1024 + m] + bb;
    }

    // q rows for this lane (fixed for whole kernel)
    int q0r = w*16 + gr, q1r = q0r + 8;
    float4 qv0, qv1;
    int kq0, kq1;
    {
        float* q0p = (float*)&qv0; float* q1p = (float*)&qv1;
        #pragma unroll
        for (int d = 0; d < 4; d++) {
            float a  = gq_g[c0 + d] * rsq;
            float bb = gq_b[c0 + d] - muq * a;
            const float* qp = g_qpool + (size_t)(b*128 + c0 + d)*1024 + n0;
            q0p[d] = (0.5f*LOG2E) * (a * qp[q0r] + bb);
            q1p[d] = (0.5f*LOG2E) * (a * qp[q1r] + bb);
        }
        int nA = n0 + q0r, nB = n0 + q1r;
        kq0 = (nA >> 8)*961 + ((nA >> 4) & 15)*31 + (nA & 15) + 3363;
        kq1 = (nB >> 8)*961 + ((nB >> 4) & 15)*31 + (nB & 15) + 3363;
    }

    const __half* vb = g_vh + (size_t)(b*128 + c0) * 16384;
    // prefetch V chunk 0
    {
        int m = tid >> 3, seg = tid & 7;
        int d = seg >> 1, p8 = (seg & 1)*8;
        cpasync16(vsm_a + (m*72 + seg*8)*2, &vb[(size_t)d*16384 + m*16 + p8]);
        int e = tid + 256;
        m = e >> 3; seg = e & 7; d = seg >> 1; p8 = (seg & 1)*8;
        cpasync16(vsm_a + (m*72 + seg*8)*2, &vb[(size_t)d*16384 + m*16 + p8]);
    }
    CP_COMMIT();
    __syncthreads();

    float acc[8][4];
    #pragma unroll
    for (int nt = 0; nt < 8; nt++)
        #pragma unroll
        for (int ci = 0; ci < 4; ci++) acc[nt][ci] = 0.f;
    float psum0 = 0.f, psum1 = 0.f;

    #pragma unroll 1
    for (int ch = 0; ch < 16; ch++) {
        int m0 = ch << 6;

        // ---- prefetch V(ch+1) via cp.async (overlaps score compute) ----
        if (ch < 15) {
            int m0n = m0 + 64;
            uint32_t vdst = vsm_a + ((ch + 1) % 3)*9216;
            #pragma unroll
            for (int it = 0; it < 2; it++) {
                int e = tid + it*256;
                int m = e >> 3, seg = e & 7;
                int d = seg >> 1, p8 = (seg & 1)*8;
                cpasync16(vdst + (m*72 + seg*8)*2,
                          &vb[(size_t)d*16384 + (m0n + m)*16 + p8]);
            }
        }
        CP_COMMIT();

        // ---- scores -> P fragments (registers only) ----
        uint32_t afr[4][4];
        #pragma unroll
        for (int ks = 0; ks < 4; ks++) {
            int mb = m0 + ks*16 + 2*cl;
            float4 kcA = ksm4[mb], kcB = ksm4[mb+1], kcC = ksm4[mb+8], kcD = ksm4[mb+9];
            int kmA = keym[mb], kmB = keym[mb+1], kmC = keym[mb+8], kmD = keym[mb+9];

            float sA0 = fmaf(qv0.x,kcA.x, fmaf(qv0.y,kcA.y, fmaf(qv0.z,kcA.z, fmaf(qv0.w,kcA.w, __half2float(tbl16[kq0-kmA])))));
            float sB0 = fmaf(qv0.x,kcB.x, fmaf(qv0.y,kcB.y, fmaf(qv0.z,kcB.z, fmaf(qv0.w,kcB.w, __half2float(tbl16[kq0-kmB])))));
            float sC0 = fmaf(qv0.x,kcC.x, fmaf(qv0.y,kcC.y, fmaf(qv0.z,kcC.z, fmaf(qv0.w,kcC.w, __half2float(tbl16[kq0-kmC])))));
            float sD0 = fmaf(qv0.x,kcD.x, fmaf(qv0.y,kcD.y, fmaf(qv0.z,kcD.z, fmaf(qv0.w,kcD.w, __half2float(tbl16[kq0-kmD])))));
            float sA1 = fmaf(qv1.x,kcA.x, fmaf(qv1.y,kcA.y, fmaf(qv1.z,kcA.z, fmaf(qv1.w,kcA.w, __half2float(tbl16[kq1-kmA])))));
            float sB1 = fmaf(qv1.x,kcB.x, fmaf(qv1.y,kcB.y, fmaf(qv1.z,kcB.z, fmaf(qv1.w,kcB.w, __half2float(tbl16[kq1-kmB])))));
            float sC1 = fmaf(qv1.x,kcC.x, fmaf(qv1.y,kcC.y, fmaf(qv1.z,kcC.z, fmaf(qv1.w,kcC.w, __half2float(tbl16[kq1-kmC])))));
            float sD1 = fmaf(qv1.x,kcD.x, fmaf(qv1.y,kcD.y, fmaf(qv1.z,kcD.z, fmaf(qv1.w,kcD.w, __half2float(tbl16[kq1-kmD])))));

            float pA0 = ex2f(sA0), pB0 = ex2f(sB0), pC0 = ex2f(sC0), pD0 = ex2f(sD0);
            float pA1 = ex2f(sA1), pB1 = ex2f(sB1), pC1 = ex2f(sC1), pD1 = ex2f(sD1);
            psum0 += (pA0 + pB0) + (pC0 + pD0);
            psum1 += (pA1 + pB1) + (pC1 + pD1);

            __half2 h0 = __floats2half2_rn(pA0, pB0);
            __half2 h1 = __floats2half2_rn(pA1, pB1);
            __half2 h2 = __floats2half2_rn(pC0, pD0);
            __half2 h3 = __floats2half2_rn(pC1, pD1);
            afr[ks][0] = *(uint32_t*)&h0;
            afr[ks][1] = *(uint32_t*)&h1;
            afr[ks][2] = *(uint32_t*)&h2;
            afr[ks][3] = *(uint32_t*)&h3;
        }

        CP_WAIT1();
        __syncthreads();

        // ---- mma: O[16q x 64dp] += P @ V(ch) ----
        uint32_t vbuf = vsm_a + (ch % 3)*9216;
        #pragma unroll
        for (int ks = 0; ks < 4; ks++) {
            #pragma unroll
            for (int np = 0; np < 4; np++) {
                uint32_t b4_0, b4_1, b4_2, b4_3;
                uint32_t adr = vbuf + ((ks*16 + (lane & 15))*72 + np*16 + ((lane >> 4) << 3))*2;
                ldsm4t(b4_0, b4_1, b4_2, b4_3, adr);
                mma_f16(acc[np*2    ], afr[ks][0], afr[ks][1], afr[ks][2], afr[ks][3], b4_0, b4_1);
                mma_f16(acc[np*2 + 1], afr[ks][0], afr[ks][1], afr[ks][2], afr[ks][3], b4_2, b4_3);
            }
        }
    }

    // ---- row sums: quad reduce (cols partitioned over cl) ----
    psum0 += __shfl_xor_sync(0xffffffffu, psum0, 1);
    psum0 += __shfl_xor_sync(0xffffffffu, psum0, 2);
    psum1 += __shfl_xor_sync(0xffffffffu, psum1, 1);
    psum1 += __shfl_xor_sync(0xffffffffu, psum1, 2);
    float invl0 = 1.f / psum0, invl1 = 1.f / psum1;

    // ---- epilogue: normalize + v-affine -> stage (reuse front smem) ----
    float av[4], bv[4];
    #pragma unroll
    for (int d = 0; d < 4; d++) {
        av[d] = gv_g[c0 + d] * rsv;
        bv[d] = gv_b[c0 + d] - muv * av[d];
    }
    float* stage = (float*)smc;     // [128][68]
    #pragma unroll
    for (int nt = 0; nt < 8; nt++) {
        int col0 = nt*8 + 2*cl;
        int d = nt >> 1;
        stage[q0r*68 + col0    ] = av[d]*(acc[nt][0]*invl0) + bv[d];
        stage[q0r*68 + col0 + 1] = av[d]*(acc[nt][1]*invl0) + bv[d];
        stage[q1r*68 + col0    ] = av[d]*(acc[nt][2]*invl1) + bv[d];
        stage[q1r*68 + col0 + 1] = av[d]*(acc[nt][3]*invl1) + bv[d];
    }
    __syncthreads();

    // ---- coalesced global write ----
    int t   = n0 >> 8;
    int hi0 = (n0 >> 4) & 15;
    #pragma unroll
    for (int it = 0; it < 32; it++) {
        int e = tid + it*256;
        int rr = e >> 6, cc = e & 63;
        int d = rr >> 5, hl = (rr >> 2) & 7, sh = rr & 3;
        int q = hl*16 + (cc >> 2);
        int dp = d*16 + sh*4 + (cc & 3);
        out[(size_t)(b*128 + c0 + d)*16384 + t*4096 + ((hi0 + hl)*4 + sh)*64 + cc]
            = stage[q*68 + dp];
    }
}

// ---------------- launcher ----------------
extern "C" void kernel_launch(void* const* d_in, const int* in_sizes, int n_in,
                              void* d_out, int out_size) {
    (void)in_sizes; (void)n_in; (void)out_size;
    const float* x    = (const float*)d_in[0];
    const float* Wq   = (const float*)d_in[1];
    const float* Wk   = (const float*)d_in[2];
    const float* Wv   = (const float*)d_in[3];
    const float* gq_g = (const float*)d_in[4];
    const float* gq_b = (const float*)d_in[5];
    const float* gk_g = (const float*)d_in[6];
    const float* gk_b = (const float*)d_in[7];
    const float* gv_g = (const float*)d_in[8];
    const float* gv_b = (const float*)d_in[9];
    const float* rel_table = (const float*)d_in[10];
    float* out = (float*)d_out;

    cudaFuncSetAttribute(proj_kernel, cudaFuncAttributeMaxDynamicSharedMemorySize, PRJ_SMEM);
    cudaFuncSetAttribute(attn_kernel, cudaFuncAttributeMaxDynamicSharedMemorySize, A2_SMEM);

    proj_kernel<<<256, 256, PRJ_SMEM>>>(x, Wq, Wk, Wv);
    attn_kernel<<<dim3(64, 8), 256, A2_SMEM>>>(gq_g, gq_b, gk_g, gk_b,
                                               gv_g, gv_b, rel_table, out);
}

// round 13
// speedup vs baseline: 14.3932x; 1.2003x over previous
#include <cuda_runtime.h>
#include <cuda_fp16.h>
#include <math.h>
#include <stdint.h>

// Problem constants
#define B_   2
#define NH   32
#define TBL  6727
#define LOG2E 1.44269504088896340736f

// ---------------- scratch ----------------
__device__ __half g_vh[B_*128*16384];      // projected v, fp16, patch layout [b][c][n*16+p]
__device__ float g_qpool[B_*128*1024];
__device__ float g_kpool[B_*128*1024];
__device__ float g_part[3*B_*NH*2*128];    // per-CTA GN stat partials

// ---------------- helpers ----------------
__device__ __forceinline__ void mma_f16(float c[4], uint32_t a0, uint32_t a1,
                                        uint32_t a2, uint32_t a3,
                                        uint32_t b0, uint32_t b1) {
    asm volatile(
        "mma.sync.aligned.m16n8k16.row.col.f32.f16.f16.f32 "
        "{%0,%1,%2,%3}, {%4,%5,%6,%7}, {%8,%9}, {%0,%1,%2,%3};"
        : "+f"(c[0]), "+f"(c[1]), "+f"(c[2]), "+f"(c[3])
        : "r"(a0), "r"(a1), "r"(a2), "r"(a3), "r"(b0), "r"(b1));
}
__device__ __forceinline__ void mma_tf32(float c[4], uint32_t a0, uint32_t a1,
                                         uint32_t a2, uint32_t a3,
                                         uint32_t b0, uint32_t b1) {
    asm volatile(
        "mma.sync.aligned.m16n8k8.row.col.f32.tf32.tf32.f32 "
        "{%0,%1,%2,%3}, {%4,%5,%6,%7}, {%8,%9}, {%0,%1,%2,%3};"
        : "+f"(c[0]), "+f"(c[1]), "+f"(c[2]), "+f"(c[3])
        : "r"(a0), "r"(a1), "r"(a2), "r"(a3), "r"(b0), "r"(b1));
}
__device__ __forceinline__ void ldsm4t(uint32_t& r0, uint32_t& r1, uint32_t& r2, uint32_t& r3,
                                       uint32_t addr) {
    asm volatile("ldmatrix.sync.aligned.m8n8.x4.trans.shared.b16 {%0,%1,%2,%3}, [%4];"
                 : "=r"(r0), "=r"(r1), "=r"(r2), "=r"(r3) : "r"(addr));
}
__device__ __forceinline__ float ex2f(float x) {
    float y;
    asm("ex2.approx.ftz.f32 %0, %1;" : "=f"(y) : "f"(x));
    return y;
}
__device__ __forceinline__ uint32_t f2tf32(float x) {
    uint32_t u;
    asm("cvt.rna.tf32.f32 %0, %1;" : "=r"(u) : "f"(x));
    return u;
}
__device__ __forceinline__ uint32_t smem_u32(const void* p) {
    uint32_t a;
    asm("{ .reg .u64 t; cvta.to.shared.u64 t, %1; cvt.u32.u64 %0, t; }" : "=r"(a) : "l"(p));
    return a;
}
__device__ __forceinline__ void cpasync16(uint32_t dst, const void* src) {
    asm volatile("cp.async.cg.shared.global [%0], [%1], 16;" :: "r"(dst), "l"(src));
}
#define CP_COMMIT() asm volatile("cp.async.commit_group;" ::: "memory")
#define CP_WAIT0()  asm volatile("cp.async.wait_group 0;" ::: "memory")

// ---------------- kernel 1: fused projections + pooling + GN partials + v store ----------------
#define PRJ_XS 0                 // half [j=128][136], col swizz c^(2*(j>>4))
#define PRJ_WS 34816             // half [o=128][136]
#define PRJ_SG 69632             // float [32][2]
#define PRJ_SMEM (69632 + 256)

__global__ void __launch_bounds__(256, 2)
proj_kernel(const float* __restrict__ x,
            const float* __restrict__ Wq,
            const float* __restrict__ Wk,
            const float* __restrict__ Wv) {
    extern __shared__ char smc[];
    __half* Xs = (__half*)(smc + PRJ_XS);
    __half* Ws = (__half*)(smc + PRJ_WS);
    float*  sg = (float*)(smc + PRJ_SG);

    int tid = threadIdx.x;
    int lane = tid & 31, w = tid >> 5;
    int gr = lane >> 2, cl = lane & 3;
    int wo = w * 16;

    int j0  = blockIdx.x * 128;
    int b   = j0 >> 14;
    int local = blockIdx.x & 127;
    int r0  = j0 & 16383;
    int n0p = r0 >> 4;
    int t   = n0p >> 8, hi = (n0p >> 4) & 15, wi0 = n0p & 15;

    // ---- load X tile coalesced, write patch-ordered [j][c] fp16 (paired c -> half2) ----
    {
        int cc = lane;
        int nl = cc >> 2, sw = cc & 3;
        const float* xb = x + (size_t)b*128*16384 + t*4096 + hi*256 + wi0*4;
        #pragma unroll 4
        for (int it = 0; it < 32; it++) {
            int grp = w + it*8;
            int cp = grp >> 2, sh = grp & 3;
            int c0 = cp * 2;
            float v0 = xb[(size_t)c0*16384 + sh*64 + cc];
            float v1 = xb[(size_t)(c0+1)*16384 + sh*64 + cc];
            int jj = nl*16 + sh*4 + sw;
            *(__half2*)&Xs[jj*136 + (c0 ^ ((jj >> 4) << 1))] = __floats2half2_rn(v0, v1);
        }
    }

    const float* Wp0[3] = {Wq, Wk, Wv};

    for (int proj = 0; proj < 3; proj++) {
        __syncthreads();
        const float* Wm = Wp0[proj];
        #pragma unroll
        for (int it = 0; it < 16; it++) {
            int e = tid + it*256;             // float4 index
            int o = e >> 5, col = (e & 31) * 4;
            float4 f4 = ((const float4*)Wm)[e];
            *(__half2*)&Ws[o*136 + col]     = __floats2half2_rn(f4.x, f4.y);
            *(__half2*)&Ws[o*136 + col + 2] = __floats2half2_rn(f4.z, f4.w);
        }
        if (tid < 64) sg[tid] = 0.f;
        __syncthreads();

        float acc[16][4];
        #pragma unroll
        for (int nt = 0; nt < 16; nt++)
            #pragma unroll
            for (int ci = 0; ci < 4; ci++) acc[nt][ci] = 0.f;

        #pragma unroll
        for (int ks = 0; ks < 8; ks++) {
            int k0 = ks*16;
            uint32_t a0 = *(uint32_t*)&Ws[(wo+gr  )*136 + k0 + 2*cl];
            uint32_t a1 = *(uint32_t*)&Ws[(wo+gr+8)*136 + k0 + 2*cl];
            uint32_t a2 = *(uint32_t*)&Ws[(wo+gr  )*136 + k0 + 2*cl + 8];
            uint32_t a3 = *(uint32_t*)&Ws[(wo+gr+8)*136 + k0 + 2*cl + 8];
            #pragma unroll
            for (int nt = 0; nt < 16; nt++) {
                int swz = (nt >> 1) << 1;
                uint32_t b0 = *(uint32_t*)&Xs[(nt*8+gr)*136 + ((k0 + 2*cl    ) ^ swz)];
                uint32_t b1 = *(uint32_t*)&Xs[(nt*8+gr)*136 + ((k0 + 2*cl + 8) ^ swz)];
                mma_f16(acc[nt], a0, a1, a2, a3, b0, b1);
            }
        }

        // ---- epilogue: pool q/k or store v ----
        if (proj < 2) {
            float* pool = (proj == 0) ? g_qpool : g_kpool;
            #pragma unroll
            for (int oh = 0; oh < 2; oh++) {
                int o = wo + gr + 8*oh;
                #pragma unroll
                for (int nl = 0; nl < 8; nl++) {
                    float s = acc[2*nl][oh*2] + acc[2*nl][oh*2+1]
                            + acc[2*nl+1][oh*2] + acc[2*nl+1][oh*2+1];
                    s += __shfl_xor_sync(0xffffffffu, s, 1);
                    s += __shfl_xor_sync(0xffffffffu, s, 2);
                    if (cl == 0)
                        pool[(size_t)(b*128 + o)*1024 + n0p + nl] = s * 0.0625f;
                }
            }
        } else {
            #pragma unroll
            for (int oh = 0; oh < 2; oh++) {
                int o = wo + gr + 8*oh;
                __half* dst = g_vh + (size_t)(b*128 + o)*16384 + r0;
                #pragma unroll
                for (int nt = 0; nt < 16; nt++) {
                    __half2 h = __floats2half2_rn(acc[nt][oh*2], acc[nt][oh*2+1]);
                    *(__half2*)&dst[nt*8 + 2*cl] = h;
                }
            }
        }

        // GN stats partials
        {
            float s0 = 0.f, q0 = 0.f, s1 = 0.f, q1 = 0.f;
            #pragma unroll
            for (int nt = 0; nt < 16; nt++) {
                float v00 = acc[nt][0], v01 = acc[nt][1];
                float v10 = acc[nt][2], v11 = acc[nt][3];
                s0 += v00 + v01; q0 += v00*v00 + v01*v01;
                s1 += v10 + v11; q1 += v10*v10 + v11*v11;
            }
            s0 += __shfl_xor_sync(0xffffffffu, s0, 1);
            s0 += __shfl_xor_sync(0xffffffffu, s0, 2);
            q0 += __shfl_xor_sync(0xffffffffu, q0, 1);
            q0 += __shfl_xor_sync(0xffffffffu, q0, 2);
            s1 += __shfl_xor_sync(0xffffffffu, s1, 1);
            s1 += __shfl_xor_sync(0xffffffffu, s1, 2);
            q1 += __shfl_xor_sync(0xffffffffu, q1, 1);
            q1 += __shfl_xor_sync(0xffffffffu, q1, 2);
            if (cl == 0) {
                int g0 = (wo + gr) >> 2, g1 = (wo + gr + 8) >> 2;
                atomicAdd(&sg[g0*2    ], s0);
                atomicAdd(&sg[g0*2 + 1], q0);
                atomicAdd(&sg[g1*2    ], s1);
                atomicAdd(&sg[g1*2 + 1], q1);
            }
        }
        __syncthreads();
        if (tid < 64)
            g_part[(((proj*B_ + b)*NH + (tid >> 1))*2 + (tid & 1))*128 + local] = sg[tid];
    }
}

// ---------------- kernel 2: attention (tensorized QK^T + register P fragments) ----------------
// byte offsets
#define A3_KSM   0        // uint32 tf32 k [m=1024][d=4] -> 16384
#define A3_TBL   16384    // half tbl16[6728] -> 29840
#define A3_ST6   29840    // float[8] -> 29872
#define A3_VSM   29888    // half V[2][64][72] -> 48320
#define A3_SMEM  48320

__global__ void __launch_bounds__(256, 4)
attn_kernel(const float* __restrict__ gq_g, const float* __restrict__ gq_b,
            const float* __restrict__ gk_g, const float* __restrict__ gk_b,
            const float* __restrict__ gv_g, const float* __restrict__ gv_b,
            const float* __restrict__ rel_table,
            float* __restrict__ out) {
    extern __shared__ char smc[];
    uint32_t* ksmu  = (uint32_t*)(smc + A3_KSM);
    __half*   tbl16 = (__half*)(smc + A3_TBL);
    float*    st6   = (float*)(smc + A3_ST6);
    uint32_t sbase = smem_u32(smc);
    uint32_t vsm_a = sbase + A3_VSM;

    int tid  = threadIdx.x;
    int w    = tid >> 5, lane = tid & 31;
    int gr   = lane >> 2, cl = lane & 3;
    int bh   = blockIdx.x;
    int b    = bh >> 5, head = bh & 31;
    int n0   = blockIdx.y << 7;
    int c0   = head * 4;

    // ---- P0: stat-partial reduce + tbl(fp16) staging ----
    if (w < 6) {
        int pr = w >> 1, s = w & 1;
        const float* gp = g_part + (size_t)(((pr*B_ + b)*NH + head)*2 + s)*128;
        float4 v = ((const float4*)gp)[lane];
        float tt = v.x + v.y + v.z + v.w;
        tt += __shfl_xor_sync(0xffffffffu, tt, 1);
        tt += __shfl_xor_sync(0xffffffffu, tt, 2);
        tt += __shfl_xor_sync(0xffffffffu, tt, 4);
        tt += __shfl_xor_sync(0xffffffffu, tt, 8);
        tt += __shfl_xor_sync(0xffffffffu, tt, 16);
        if (lane == 0) st6[pr*2 + s] = tt;
    }
    for (int e = tid; e < TBL; e += 256) tbl16[e] = __float2half(rel_table[head*TBL + e] * LOG2E);
    __syncthreads();

    // ---- P1: GN constants, tf32 k staging, q fragments, V(0) prefetch ----
    float muq = st6[0]*(1.f/65536.f), rsq = rsqrtf(st6[1]*(1.f/65536.f) - muq*muq + 1e-5f);
    float muk = st6[2]*(1.f/65536.f), rsk = rsqrtf(st6[3]*(1.f/65536.f) - muk*muk + 1e-5f);
    float muv = st6[4]*(1.f/65536.f), rsv = rsqrtf(st6[5]*(1.f/65536.f) - muv*muv + 1e-5f);

    #pragma unroll
    for (int it = 0; it < 16; it++) {
        int d = it >> 2;
        int m = tid + (it & 3)*256;
        float a  = gk_g[c0 + d] * rsk;
        float bb = gk_b[c0 + d] - muk * a;
        ksmu[m*4 + d] = f2tf32(a * g_kpool[(size_t)(b*128 + c0 + d)*1024 + m] + bb);
    }

    // q fragment regs (tf32, scale folded); this lane carries d = cl only
    int q0r = w*16 + gr, q1r = q0r + 8;
    uint32_t qa0, qa1;
    int kq0, kq1;
    {
        float a  = gq_g[c0 + cl] * rsq;
        float bb = gq_b[c0 + cl] - muq * a;
        const float* qp = g_qpool + (size_t)(b*128 + c0 + cl)*1024 + n0;
        qa0 = f2tf32((0.5f*LOG2E) * (a * qp[q0r] + bb));
        qa1 = f2tf32((0.5f*LOG2E) * (a * qp[q1r] + bb));
        int nA = n0 + q0r, nB = n0 + q1r;
        kq0 = (nA >> 8)*961 + ((nA >> 4) & 15)*31 + (nA & 15) + 3363;
        kq1 = (nB >> 8)*961 + ((nB >> 4) & 15)*31 + (nB & 15) + 3363;
    }

    const __half* vb = g_vh + (size_t)(b*128 + c0) * 16384;
    // prefetch V chunk 0 into buffer 0
    #pragma unroll
    for (int it = 0; it < 2; it++) {
        int e = tid + it*256;
        int m = e >> 3, seg = e & 7;
        int d = seg >> 1, p8 = (seg & 1)*8;
        cpasync16(vsm_a + (m*72 + seg*8)*2, &vb[(size_t)d*16384 + m*16 + p8]);
    }
    CP_COMMIT();

    float acc[8][4];
    #pragma unroll
    for (int nt = 0; nt < 8; nt++)
        #pragma unroll
        for (int ci = 0; ci < 4; ci++) acc[nt][ci] = 0.f;
    float psum0 = 0.f, psum1 = 0.f;

    #pragma unroll 1
    for (int ch = 0; ch < 16; ch++) {
        int m0 = ch << 6;

        CP_WAIT0();
        __syncthreads();           // V(ch) landed; all warps done with V((ch+1)&1)

        // prefetch V(ch+1) — overlaps with this chunk's compute
        if (ch < 15) {
            int m0n = m0 + 64;
            uint32_t vdst = vsm_a + ((ch + 1) & 1)*9216;
            #pragma unroll
            for (int it = 0; it < 2; it++) {
                int e = tid + it*256;
                int m = e >> 3, seg = e & 7;
                int d = seg >> 1, p8 = (seg & 1)*8;
                cpasync16(vdst + (m*72 + seg*8)*2,
                          &vb[(size_t)d*16384 + (m0n + m)*16 + p8]);
            }
            CP_COMMIT();
        }

        int key_c = (m0 >> 8)*961 + ((m0 >> 4) & 15)*31;
        int i0b = kq0 - key_c - 2*cl;
        int i1b = kq1 - key_c - 2*cl;
        uint32_t vbuf = vsm_a + (ch & 1)*9216;

        #pragma unroll
        for (int ks = 0; ks < 4; ks++) {
            // QK^T on tensor pipe: two m16n8k8 tf32 mmas (m-blocks 2ks, 2ks+1)
            uint32_t kb0 = ksmu[(m0 + ks*16 +     gr)*4 + cl];
            uint32_t kb1 = ksmu[(m0 + ks*16 + 8 + gr)*4 + cl];
            float ce[4] = {0.f,0.f,0.f,0.f}, co[4] = {0.f,0.f,0.f,0.f};
            mma_tf32(ce, qa0, qa1, 0u, 0u, kb0, 0u);
            mma_tf32(co, qa0, qa1, 0u, 0u, kb1, 0u);

            int ie = i0b - ks*31;      // q0, even block
            int je = i1b - ks*31;      // q1, even block
            int io = ie - 8, jo = je - 8;

            float p00 = ex2f(ce[0] + __half2float(tbl16[ie    ]));
            float p01 = ex2f(ce[1] + __half2float(tbl16[ie - 1]));
            float p10 = ex2f(ce[2] + __half2float(tbl16[je    ]));
            float p11 = ex2f(ce[3] + __half2float(tbl16[je - 1]));
            float p02 = ex2f(co[0] + __half2float(tbl16[io    ]));
            float p03 = ex2f(co[1] + __half2float(tbl16[io - 1]));
            float p12 = ex2f(co[2] + __half2float(tbl16[jo    ]));
            float p13 = ex2f(co[3] + __half2float(tbl16[jo - 1]));
            psum0 += (p00 + p01) + (p02 + p03);
            psum1 += (p10 + p11) + (p12 + p13);

            __half2 h0 = __floats2half2_rn(p00, p01);
            __half2 h1 = __floats2half2_rn(p10, p11);
            __half2 h2 = __floats2half2_rn(p02, p03);
            __half2 h3 = __floats2half2_rn(p12, p13);
            uint32_t f0 = *(uint32_t*)&h0, f1 = *(uint32_t*)&h1;
            uint32_t f2 = *(uint32_t*)&h2, f3 = *(uint32_t*)&h3;

            // PV: O[16q x 64dp] += P(ks) @ V(ch)
            #pragma unroll
            for (int np = 0; np < 4; np++) {
                uint32_t b0, b1, b2, b3;
                uint32_t adr = vbuf + ((ks*16 + (lane & 15))*72 + np*16 + ((lane >> 4) << 3))*2;
                ldsm4t(b0, b1, b2, b3, adr);
                mma_f16(acc[np*2    ], f0, f1, f2, f3, b0, b1);
                mma_f16(acc[np*2 + 1], f0, f1, f2, f3, b2, b3);
            }
        }
    }
    __syncthreads();   // all warps done reading ksm/tbl/V before stage overwrite

    // ---- row sums: quad reduce (m-cols partitioned over cl) ----
    psum0 += __shfl_xor_sync(0xffffffffu, psum0, 1);
    psum0 += __shfl_xor_sync(0xffffffffu, psum0, 2);
    psum1 += __shfl_xor_sync(0xffffffffu, psum1, 1);
    psum1 += __shfl_xor_sync(0xffffffffu, psum1, 2);
    float invl0 = 1.f / psum0, invl1 = 1.f / psum1;

    // ---- epilogue: normalize + v-affine -> stage ----
    float av[4], bv[4];
    #pragma unroll
    for (int d = 0; d < 4; d++) {
        av[d] = gv_g[c0 + d] * rsv;
        bv[d] = gv_b[c0 + d] - muv * av[d];
    }
    float* stage = (float*)smc;     // [128][68]
    #pragma unroll
    for (int nt = 0; nt < 8; nt++) {
        int col0 = nt*8 + 2*cl;
        int d = nt >> 1;
        stage[q0r*68 + col0    ] = av[d]*(acc[nt][0]*invl0) + bv[d];
        stage[q0r*68 + col0 + 1] = av[d]*(acc[nt][1]*invl0) + bv[d];
        stage[q1r*68 + col0    ] = av[d]*(acc[nt][2]*invl1) + bv[d];
        stage[q1r*68 + col0 + 1] = av[d]*(acc[nt][3]*invl1) + bv[d];
    }
    __syncthreads();

    // ---- coalesced global write ----
    int t   = n0 >> 8;
    int hi0 = (n0 >> 4) & 15;
    #pragma unroll
    for (int it = 0; it < 32; it++) {
        int e = tid + it*256;
        int rr = e >> 6, cc = e & 63;
        int d = rr >> 5, hl = (rr >> 2) & 7, sh = rr & 3;
        int q = hl*16 + (cc >> 2);
        int dp = d*16 + sh*4 + (cc & 3);
        out[(size_t)(b*128 + c0 + d)*16384 + t*4096 + ((hi0 + hl)*4 + sh)*64 + cc]
            = stage[q*68 + dp];
    }
}

// ---------------- launcher ----------------
extern "C" void kernel_launch(void* const* d_in, const int* in_sizes, int n_in,
                              void* d_out, int out_size) {
    (void)in_sizes; (void)n_in; (void)out_size;
    const float* x    = (const float*)d_in[0];
    const float* Wq   = (const float*)d_in[1];
    const float* Wk   = (const float*)d_in[2];
    const float* Wv   = (const float*)d_in[3];
    const float* gq_g = (const float*)d_in[4];
    const float* gq_b = (const float*)d_in[5];
    const float* gk_g = (const float*)d_in[6];
    const float* gk_b = (const float*)d_in[7];
    const float* gv_g = (const float*)d_in[8];
    const float* gv_b = (const float*)d_in[9];
    const float* rel_table = (const float*)d_in[10];
    float* out = (float*)d_out;

    cudaFuncSetAttribute(proj_kernel, cudaFuncAttributeMaxDynamicSharedMemorySize, PRJ_SMEM);
    cudaFuncSetAttribute(attn_kernel, cudaFuncAttributeMaxDynamicSharedMemorySize, A3_SMEM);

    proj_kernel<<<256, 256, PRJ_SMEM>>>(x, Wq, Wk, Wv);
    attn_kernel<<<dim3(64, 8), 256, A3_SMEM>>>(gq_g, gq_b, gk_g, gk_b,
                                               gv_g, gv_b, rel_table, out);
}

// round 14
// speedup vs baseline: 16.3441x; 1.1355x over previous
#include <cuda_runtime.h>
#include <cuda_fp16.h>
#include <math.h>
#include <stdint.h>

// Problem constants
#define B_   2
#define NH   32
#define TBL  6727
#define LOG2E 1.44269504088896340736f

// ---------------- scratch ----------------
__device__ __half g_vh[B_*128*16384];      // projected v, fp16, patch layout [b][c][n*16+p]
__device__ float g_qpool[B_*128*1024];
__device__ float g_kpool[B_*128*1024];
__device__ float g_part[3*B_*NH*2*128];    // per-CTA GN stat partials
__device__ __half g_wh[3*128*136];         // fp16 W, padded [proj][o][136]

// ---------------- helpers ----------------
__device__ __forceinline__ void mma_f16(float c[4], uint32_t a0, uint32_t a1,
                                        uint32_t a2, uint32_t a3,
                                        uint32_t b0, uint32_t b1) {
    asm volatile(
        "mma.sync.aligned.m16n8k16.row.col.f32.f16.f16.f32 "
        "{%0,%1,%2,%3}, {%4,%5,%6,%7}, {%8,%9}, {%0,%1,%2,%3};"
        : "+f"(c[0]), "+f"(c[1]), "+f"(c[2]), "+f"(c[3])
        : "r"(a0), "r"(a1), "r"(a2), "r"(a3), "r"(b0), "r"(b1));
}
__device__ __forceinline__ void mma_tf32(float c[4], uint32_t a0, uint32_t a1,
                                         uint32_t a2, uint32_t a3,
                                         uint32_t b0, uint32_t b1) {
    asm volatile(
        "mma.sync.aligned.m16n8k8.row.col.f32.tf32.tf32.f32 "
        "{%0,%1,%2,%3}, {%4,%5,%6,%7}, {%8,%9}, {%0,%1,%2,%3};"
        : "+f"(c[0]), "+f"(c[1]), "+f"(c[2]), "+f"(c[3])
        : "r"(a0), "r"(a1), "r"(a2), "r"(a3), "r"(b0), "r"(b1));
}
__device__ __forceinline__ void ldsm4t(uint32_t& r0, uint32_t& r1, uint32_t& r2, uint32_t& r3,
                                       uint32_t addr) {
    asm volatile("ldmatrix.sync.aligned.m8n8.x4.trans.shared.b16 {%0,%1,%2,%3}, [%4];"
                 : "=r"(r0), "=r"(r1), "=r"(r2), "=r"(r3) : "r"(addr));
}
__device__ __forceinline__ uint32_t ex2h2(uint32_t x) {
    uint32_t y;
    asm("ex2.approx.f16x2 %0, %1;" : "=r"(y) : "r"(x));
    return y;
}
__device__ __forceinline__ uint32_t f2tf32(float x) {
    uint32_t u;
    asm("cvt.rna.tf32.f32 %0, %1;" : "=r"(u) : "f"(x));
    return u;
}
__device__ __forceinline__ uint32_t smem_u32(const void* p) {
    uint32_t a;
    asm("{ .reg .u64 t; cvta.to.shared.u64 t, %1; cvt.u32.u64 %0, t; }" : "=r"(a) : "l"(p));
    return a;
}
__device__ __forceinline__ void cpasync16(uint32_t dst, const void* src) {
    asm volatile("cp.async.cg.shared.global [%0], [%1], 16;" :: "r"(dst), "l"(src));
}
#define CP_COMMIT() asm volatile("cp.async.commit_group;" ::: "memory")
#define CP_WAIT0()  asm volatile("cp.async.wait_group 0;" ::: "memory")

// ---------------- kernel 0: W -> fp16 padded layout ----------------
__global__ void whalf_kernel(const float* __restrict__ Wq,
                             const float* __restrict__ Wk,
                             const float* __restrict__ Wv) {
    int e = blockIdx.x * 256 + threadIdx.x;
    if (e < 3*16384) {
        int p = e >> 14, le = e & 16383;
        const float* W = (p == 0) ? Wq : (p == 1 ? Wk : Wv);
        int o = le >> 7, c = le & 127;
        g_wh[p*128*136 + o*136 + c] = __float2half(W[le]);
    }
}

// ---------------- kernel 1: fused projections + pooling + GN partials + v store ----------------
#define PRJ_XS 0                 // half [j=128][136], col swizz c^(2*(j>>4))
#define PRJ_W0 34816             // half [o=128][136] double-buffered
#define PRJ_W1 69632
#define PRJ_SG 104448            // float [32][2]
#define PRJ_SMEM (104448 + 256)

__global__ void __launch_bounds__(256, 2)
proj_kernel(const float* __restrict__ x) {
    extern __shared__ char smc[];
    __half* Xs = (__half*)(smc + PRJ_XS);
    float*  sg = (float*)(smc + PRJ_SG);
    uint32_t sbase = smem_u32(smc);

    int tid = threadIdx.x;
    int lane = tid & 31, w = tid >> 5;
    int gr = lane >> 2, cl = lane & 3;
    int wo = w * 16;

    int j0  = blockIdx.x * 128;
    int b   = j0 >> 14;
    int local = blockIdx.x & 127;
    int r0  = j0 & 16383;
    int n0p = r0 >> 4;
    int t   = n0p >> 8, hi = (n0p >> 4) & 15, wi0 = n0p & 15;

    // prefetch W(0) via cp.async (overlaps X staging below)
    {
        const char* src = (const char*)g_wh;
        uint32_t dst = sbase + PRJ_W0;
        #pragma unroll
        for (int it = 0; it < 9; it++) {
            int i = tid + it*256;
            if (i < 2176) cpasync16(dst + i*16, src + i*16);
        }
        CP_COMMIT();
    }

    // ---- load X tile coalesced, write patch-ordered [j][c] fp16 (paired c -> half2) ----
    {
        int cc = lane;
        int nl = cc >> 2, sw = cc & 3;
        const float* xb = x + (size_t)b*128*16384 + t*4096 + hi*256 + wi0*4;
        #pragma unroll 4
        for (int it = 0; it < 32; it++) {
            int grp = w + it*8;
            int cp = grp >> 2, sh = grp & 3;
            int c0 = cp * 2;
            float v0 = xb[(size_t)c0*16384 + sh*64 + cc];
            float v1 = xb[(size_t)(c0+1)*16384 + sh*64 + cc];
            int jj = nl*16 + sh*4 + sw;
            *(__half2*)&Xs[jj*136 + (c0 ^ ((jj >> 4) << 1))] = __floats2half2_rn(v0, v1);
        }
    }

    for (int proj = 0; proj < 3; proj++) {
        CP_WAIT0();                       // W(proj) landed
        if (tid < 64) sg[tid] = 0.f;
        __syncthreads();                  // X + W(proj) + sg visible; prev epilogue done

        // prefetch W(proj+1) into the other buffer — overlaps mma below
        if (proj < 2) {
            const char* src = (const char*)g_wh + (proj + 1)*34816;
            uint32_t dst = sbase + (((proj + 1) & 1) ? PRJ_W1 : PRJ_W0);
            #pragma unroll
            for (int it = 0; it < 9; it++) {
                int i = tid + it*256;
                if (i < 2176) cpasync16(dst + i*16, src + i*16);
            }
            CP_COMMIT();
        }

        __half* Ws = (__half*)(smc + ((proj & 1) ? PRJ_W1 : PRJ_W0));

        float acc[16][4];
        #pragma unroll
        for (int nt = 0; nt < 16; nt++)
            #pragma unroll
            for (int ci = 0; ci < 4; ci++) acc[nt][ci] = 0.f;

        #pragma unroll
        for (int ks = 0; ks < 8; ks++) {
            int k0 = ks*16;
            uint32_t a0 = *(uint32_t*)&Ws[(wo+gr  )*136 + k0 + 2*cl];
            uint32_t a1 = *(uint32_t*)&Ws[(wo+gr+8)*136 + k0 + 2*cl];
            uint32_t a2 = *(uint32_t*)&Ws[(wo+gr  )*136 + k0 + 2*cl + 8];
            uint32_t a3 = *(uint32_t*)&Ws[(wo+gr+8)*136 + k0 + 2*cl + 8];
            #pragma unroll
            for (int nt = 0; nt < 16; nt++) {
                int swz = (nt >> 1) << 1;
                uint32_t b0 = *(uint32_t*)&Xs[(nt*8+gr)*136 + ((k0 + 2*cl    ) ^ swz)];
                uint32_t b1 = *(uint32_t*)&Xs[(nt*8+gr)*136 + ((k0 + 2*cl + 8) ^ swz)];
                mma_f16(acc[nt], a0, a1, a2, a3, b0, b1);
            }
        }

        // ---- epilogue: pool q/k or store v ----
        if (proj < 2) {
            float* pool = (proj == 0) ? g_qpool : g_kpool;
            #pragma unroll
            for (int oh = 0; oh < 2; oh++) {
                int o = wo + gr + 8*oh;
                #pragma unroll
                for (int nl = 0; nl < 8; nl++) {
                    float s = acc[2*nl][oh*2] + acc[2*nl][oh*2+1]
                            + acc[2*nl+1][oh*2] + acc[2*nl+1][oh*2+1];
                    s += __shfl_xor_sync(0xffffffffu, s, 1);
                    s += __shfl_xor_sync(0xffffffffu, s, 2);
                    if (cl == 0)
                        pool[(size_t)(b*128 + o)*1024 + n0p + nl] = s * 0.0625f;
                }
            }
        } else {
            #pragma unroll
            for (int oh = 0; oh < 2; oh++) {
                int o = wo + gr + 8*oh;
                __half* dst = g_vh + (size_t)(b*128 + o)*16384 + r0;
                #pragma unroll
                for (int nt = 0; nt < 16; nt++) {
                    __half2 h = __floats2half2_rn(acc[nt][oh*2], acc[nt][oh*2+1]);
                    *(__half2*)&dst[nt*8 + 2*cl] = h;
                }
            }
        }

        // GN stats partials
        {
            float s0 = 0.f, q0 = 0.f, s1 = 0.f, q1 = 0.f;
            #pragma unroll
            for (int nt = 0; nt < 16; nt++) {
                float v00 = acc[nt][0], v01 = acc[nt][1];
                float v10 = acc[nt][2], v11 = acc[nt][3];
                s0 += v00 + v01; q0 += v00*v00 + v01*v01;
                s1 += v10 + v11; q1 += v10*v10 + v11*v11;
            }
            s0 += __shfl_xor_sync(0xffffffffu, s0, 1);
            s0 += __shfl_xor_sync(0xffffffffu, s0, 2);
            q0 += __shfl_xor_sync(0xffffffffu, q0, 1);
            q0 += __shfl_xor_sync(0xffffffffu, q0, 2);
            s1 += __shfl_xor_sync(0xffffffffu, s1, 1);
            s1 += __shfl_xor_sync(0xffffffffu, s1, 2);
            q1 += __shfl_xor_sync(0xffffffffu, q1, 1);
            q1 += __shfl_xor_sync(0xffffffffu, q1, 2);
            if (cl == 0) {
                int g0 = (wo + gr) >> 2, g1 = (wo + gr + 8) >> 2;
                atomicAdd(&sg[g0*2    ], s0);
                atomicAdd(&sg[g0*2 + 1], q0);
                atomicAdd(&sg[g1*2    ], s1);
                atomicAdd(&sg[g1*2 + 1], q1);
            }
        }
        __syncthreads();
        if (tid < 64)
            g_part[(((proj*B_ + b)*NH + (tid >> 1))*2 + (tid & 1))*128 + local] = sg[tid];
    }
}

// ---------------- kernel 2: attention (tensorized QK^T + f16x2 exp) ----------------
// byte offsets
#define A3_KSM   0        // uint32 tf32 k [m=1024][d=4] -> 16384
#define A3_TBL   16384    // half tbl16[6728] -> 29840
#define A3_ST6   29840    // float[8] -> 29872
#define A3_VSM   29888    // half V[2][64][72] -> 48320
#define A3_SMEM  48320

__global__ void __launch_bounds__(256, 4)
attn_kernel(const float* __restrict__ gq_g, const float* __restrict__ gq_b,
            const float* __restrict__ gk_g, const float* __restrict__ gk_b,
            const float* __restrict__ gv_g, const float* __restrict__ gv_b,
            const float* __restrict__ rel_table,
            float* __restrict__ out) {
    extern __shared__ char smc[];
    uint32_t* ksmu  = (uint32_t*)(smc + A3_KSM);
    __half*   tbl16 = (__half*)(smc + A3_TBL);
    float*    st6   = (float*)(smc + A3_ST6);
    uint32_t sbase = smem_u32(smc);
    uint32_t vsm_a = sbase + A3_VSM;

    int tid  = threadIdx.x;
    int w    = tid >> 5, lane = tid & 31;
    int gr   = lane >> 2, cl = lane & 3;
    int bh   = blockIdx.x;
    int b    = bh >> 5, head = bh & 31;
    int n0   = blockIdx.y << 7;
    int c0   = head * 4;

    // ---- P0: stat-partial reduce + tbl(fp16) staging ----
    if (w < 6) {
        int pr = w >> 1, s = w & 1;
        const float* gp = g_part + (size_t)(((pr*B_ + b)*NH + head)*2 + s)*128;
        float4 v = ((const float4*)gp)[lane];
        float tt = v.x + v.y + v.z + v.w;
        tt += __shfl_xor_sync(0xffffffffu, tt, 1);
        tt += __shfl_xor_sync(0xffffffffu, tt, 2);
        tt += __shfl_xor_sync(0xffffffffu, tt, 4);
        tt += __shfl_xor_sync(0xffffffffu, tt, 8);
        tt += __shfl_xor_sync(0xffffffffu, tt, 16);
        if (lane == 0) st6[pr*2 + s] = tt;
    }
    for (int e = tid; e < TBL; e += 256) tbl16[e] = __float2half(rel_table[head*TBL + e] * LOG2E);
    __syncthreads();

    // ---- P1: GN constants, tf32 k staging, q fragments, V(0) prefetch ----
    float muq = st6[0]*(1.f/65536.f), rsq = rsqrtf(st6[1]*(1.f/65536.f) - muq*muq + 1e-5f);
    float muk = st6[2]*(1.f/65536.f), rsk = rsqrtf(st6[3]*(1.f/65536.f) - muk*muk + 1e-5f);
    float muv = st6[4]*(1.f/65536.f), rsv = rsqrtf(st6[5]*(1.f/65536.f) - muv*muv + 1e-5f);

    #pragma unroll
    for (int it = 0; it < 16; it++) {
        int d = it >> 2;
        int m = tid + (it & 3)*256;
        float a  = gk_g[c0 + d] * rsk;
        float bb = gk_b[c0 + d] - muk * a;
        ksmu[m*4 + d] = f2tf32(a * g_kpool[(size_t)(b*128 + c0 + d)*1024 + m] + bb);
    }

    // q fragment regs (tf32, scale folded); this lane carries d = cl only
    int q0r = w*16 + gr, q1r = q0r + 8;
    uint32_t qa0, qa1;
    int kq0, kq1;
    {
        float a  = gq_g[c0 + cl] * rsq;
        float bb = gq_b[c0 + cl] - muq * a;
        const float* qp = g_qpool + (size_t)(b*128 + c0 + cl)*1024 + n0;
        qa0 = f2tf32((0.5f*LOG2E) * (a * qp[q0r] + bb));
        qa1 = f2tf32((0.5f*LOG2E) * (a * qp[q1r] + bb));
        int nA = n0 + q0r, nB = n0 + q1r;
        kq0 = (nA >> 8)*961 + ((nA >> 4) & 15)*31 + (nA & 15) + 3363;
        kq1 = (nB >> 8)*961 + ((nB >> 4) & 15)*31 + (nB & 15) + 3363;
    }

    const __half* vb = g_vh + (size_t)(b*128 + c0) * 16384;
    // prefetch V chunk 0 into buffer 0
    #pragma unroll
    for (int it = 0; it < 2; it++) {
        int e = tid + it*256;
        int m = e >> 3, seg = e & 7;
        int d = seg >> 1, p8 = (seg & 1)*8;
        cpasync16(vsm_a + (m*72 + seg*8)*2, &vb[(size_t)d*16384 + m*16 + p8]);
    }
    CP_COMMIT();

    float acc[8][4];
    #pragma unroll
    for (int nt = 0; nt < 8; nt++)
        #pragma unroll
        for (int ci = 0; ci < 4; ci++) acc[nt][ci] = 0.f;
    float psum0 = 0.f, psum1 = 0.f;

    #pragma unroll 1
    for (int ch = 0; ch < 16; ch++) {
        int m0 = ch << 6;

        CP_WAIT0();
        __syncthreads();           // V(ch) landed; all warps done with V((ch+1)&1)

        // prefetch V(ch+1) — overlaps with this chunk's compute
        if (ch < 15) {
            int m0n = m0 + 64;
            uint32_t vdst = vsm_a + ((ch + 1) & 1)*9216;
            #pragma unroll
            for (int it = 0; it < 2; it++) {
                int e = tid + it*256;
                int m = e >> 3, seg = e & 7;
                int d = seg >> 1, p8 = (seg & 1)*8;
                cpasync16(vdst + (m*72 + seg*8)*2,
                          &vb[(size_t)d*16384 + (m0n + m)*16 + p8]);
            }
            CP_COMMIT();
        }

        int key_c = (m0 >> 8)*961 + ((m0 >> 4) & 15)*31;
        int i0b = kq0 - key_c - 2*cl;
        int i1b = kq1 - key_c - 2*cl;
        uint32_t vbuf = vsm_a + (ch & 1)*9216;

        #pragma unroll
        for (int ks = 0; ks < 4; ks++) {
            // QK^T on tensor pipe: two m16n8k8 tf32 mmas (m-blocks 2ks, 2ks+1)
            uint32_t kb0 = ksmu[(m0 + ks*16 +     gr)*4 + cl];
            uint32_t kb1 = ksmu[(m0 + ks*16 + 8 + gr)*4 + cl];
            float ce[4] = {0.f,0.f,0.f,0.f}, co[4] = {0.f,0.f,0.f,0.f};
            mma_tf32(ce, qa0, qa1, 0u, 0u, kb0, 0u);
            mma_tf32(co, qa0, qa1, 0u, 0u, kb1, 0u);

            int ie = i0b - ks*31;      // q0, even block
            int je = i1b - ks*31;      // q1, even block
            int io = ie - 8, jo = je - 8;

            // bias add + exp in half2 domain (ex2.approx.f16x2)
            __half2 s00 = __hadd2(__floats2half2_rn(ce[0], ce[1]),
                                  __halves2half2(tbl16[ie], tbl16[ie - 1]));
            __half2 s10 = __hadd2(__floats2half2_rn(ce[2], ce[3]),
                                  __halves2half2(tbl16[je], tbl16[je - 1]));
            __half2 s01 = __hadd2(__floats2half2_rn(co[0], co[1]),
                                  __halves2half2(tbl16[io], tbl16[io - 1]));
            __half2 s11 = __hadd2(__floats2half2_rn(co[2], co[3]),
                                  __halves2half2(tbl16[jo], tbl16[jo - 1]));
            uint32_t f0 = ex2h2(*(uint32_t*)&s00);
            uint32_t f1 = ex2h2(*(uint32_t*)&s10);
            uint32_t f2 = ex2h2(*(uint32_t*)&s01);
            uint32_t f3 = ex2h2(*(uint32_t*)&s11);

            // row sums: pairwise half2 add (≤2 values/component), then fp32 accumulate
            {
                __half2 h02 = __hadd2(*(__half2*)&f0, *(__half2*)&f2);
                __half2 h13 = __hadd2(*(__half2*)&f1, *(__half2*)&f3);
                float2 a0f = __half22float2(h02);
                float2 a1f = __half22float2(h13);
                psum0 += a0f.x + a0f.y;
                psum1 += a1f.x + a1f.y;
            }

            // PV: O[16q x 64dp] += P(ks) @ V(ch)
            #pragma unroll
            for (int np = 0; np < 4; np++) {
                uint32_t b0, b1, b2, b3;
                uint32_t adr = vbuf + ((ks*16 + (lane & 15))*72 + np*16 + ((lane >> 4) << 3))*2;
                ldsm4t(b0, b1, b2, b3, adr);
                mma_f16(acc[np*2    ], f0, f1, f2, f3, b0, b1);
                mma_f16(acc[np*2 + 1], f0, f1, f2, f3, b2, b3);
            }
        }
    }
    __syncthreads();   // all warps done reading ksm/tbl/V before stage overwrite

    // ---- row sums: quad reduce (m-cols partitioned over cl) ----
    psum0 += __shfl_xor_sync(0xffffffffu, psum0, 1);
    psum0 += __shfl_xor_sync(0xffffffffu, psum0, 2);
    psum1 += __shfl_xor_sync(0xffffffffu, psum1, 1);
    psum1 += __shfl_xor_sync(0xffffffffu, psum1, 2);
    float invl0 = 1.f / psum0, invl1 = 1.f / psum1;

    // ---- epilogue: normalize + v-affine -> stage ----
    float av[4], bv[4];
    #pragma unroll
    for (int d = 0; d < 4; d++) {
        av[d] = gv_g[c0 + d] * rsv;
        bv[d] = gv_b[c0 + d] - muv * av[d];
    }
    float* stage = (float*)smc;     // [128][68]
    #pragma unroll
    for (int nt = 0; nt < 8; nt++) {
        int col0 = nt*8 + 2*cl;
        int d = nt >> 1;
        stage[q0r*68 + col0    ] = av[d]*(acc[nt][0]*invl0) + bv[d];
        stage[q0r*68 + col0 + 1] = av[d]*(acc[nt][1]*invl0) + bv[d];
        stage[q1r*68 + col0    ] = av[d]*(acc[nt][2]*invl1) + bv[d];
        stage[q1r*68 + col0 + 1] = av[d]*(acc[nt][3]*invl1) + bv[d];
    }
    __syncthreads();

    // ---- coalesced global write ----
    int t   = n0 >> 8;
    int hi0 = (n0 >> 4) & 15;
    #pragma unroll
    for (int it = 0; it < 32; it++) {
        int e = tid + it*256;
        int rr = e >> 6, cc = e & 63;
        int d = rr >> 5, hl = (rr >> 2) & 7, sh = rr & 3;
        int q = hl*16 + (cc >> 2);
        int dp = d*16 + sh*4 + (cc & 3);
        out[(size_t)(b*128 + c0 + d)*16384 + t*4096 + ((hi0 + hl)*4 + sh)*64 + cc]
            = stage[q*68 + dp];
    }
}

// ---------------- launcher ----------------
extern "C" void kernel_launch(void* const* d_in, const int* in_sizes, int n_in,
                              void* d_out, int out_size) {
    (void)in_sizes; (void)n_in; (void)out_size;
    const float* x    = (const float*)d_in[0];
    const float* Wq   = (const float*)d_in[1];
    const float* Wk   = (const float*)d_in[2];
    const float* Wv   = (const float*)d_in[3];
    const float* gq_g = (const float*)d_in[4];
    const float* gq_b = (const float*)d_in[5];
    const float* gk_g = (const float*)d_in[6];
    const float* gk_b = (const float*)d_in[7];
    const float* gv_g = (const float*)d_in[8];
    const float* gv_b = (const float*)d_in[9];
    const float* rel_table = (const float*)d_in[10];
    float* out = (float*)d_out;

    cudaFuncSetAttribute(proj_kernel, cudaFuncAttributeMaxDynamicSharedMemorySize, PRJ_SMEM);
    cudaFuncSetAttribute(attn_kernel, cudaFuncAttributeMaxDynamicSharedMemorySize, A3_SMEM);

    whalf_kernel<<<192, 256>>>(Wq, Wk, Wv);
    proj_kernel<<<256, 256, PRJ_SMEM>>>(x);
    attn_kernel<<<dim3(64, 8), 256, A3_SMEM>>>(gq_g, gq_b, gk_g, gk_b,
                                               gv_g, gv_b, rel_table, out);
}